// round 1
// baseline (speedup 1.0000x reference)
#include <cuda_runtime.h>
#include <cuda_bf16.h>
#include <math.h>

// ---------------------------------------------------------------------------
// Problem constants
// ---------------------------------------------------------------------------
#define T_TOK   8192
#define HIDDEN  4096
#define NHEAD   16
#define HD      256
#define QKV_W   (3 * HIDDEN)     // 12288
#define BATCH   8
#define SEQ     1024
#define ROT_H   32               // rotary_dim/2

// Scratch (device globals: allocation-free rule)
__device__ float g_qkv[(size_t)T_TOK * QKV_W];     // 8192 x 12288
__device__ float g_attn[(size_t)T_TOK * HIDDEN];   // 8192 x 4096

// ---------------------------------------------------------------------------
// tf32 helpers
// ---------------------------------------------------------------------------
__device__ __forceinline__ unsigned f2tf32(float x) {
    unsigned u;
    asm("cvt.rna.tf32.f32 %0, %1;" : "=r"(u) : "f"(x));
    return u;
}

__device__ __forceinline__ void mma_tf32(float* d, const unsigned* a, const unsigned* b) {
    asm volatile(
        "mma.sync.aligned.m16n8k8.row.col.f32.tf32.tf32.f32 "
        "{%0,%1,%2,%3}, {%4,%5,%6,%7}, {%8,%9}, {%0,%1,%2,%3};\n"
        : "+f"(d[0]), "+f"(d[1]), "+f"(d[2]), "+f"(d[3])
        : "r"(a[0]), "r"(a[1]), "r"(a[2]), "r"(a[3]),
          "r"(b[0]), "r"(b[1]));
}

// ---------------------------------------------------------------------------
// GEMM (NT): C[M][N] = sum_k A[M][K] * B[N][K]   (both row-major, K contiguous)
// Tiles: 128x128x32, 256 threads (8 warps, 4x2 warp grid), tf32 mma m16n8k8.
// Smem holds tiles in *fragment order*: each lane's fragment regs contiguous.
// ---------------------------------------------------------------------------
__global__ __launch_bounds__(256) void gemm_tf32_nt(
    const float* __restrict__ A, const float* __restrict__ B,
    float* __restrict__ C, int M, int N, int K)
{
    __shared__ __align__(16) unsigned As[4][8][32][4];   // [k8][m16][lane][reg]
    __shared__ __align__(16) unsigned Bs[4][16][32][2];  // [k8][n8][lane][reg]

    const int tid  = threadIdx.x;
    const int lane = tid & 31;
    const int warp = tid >> 5;
    const int wr   = warp >> 1;   // 0..3
    const int wc   = warp & 1;    // 0..1

    // CTA swizzle: 8 m-rows per group so weight panels stay L2-resident
    const int Nb = gridDim.x;
    const int Mb = gridDim.y;
    int linear = blockIdx.y * Nb + blockIdx.x;
    int group  = linear / (Nb * 8);
    int rem    = linear - group * (Nb * 8);
    int mstart = group * 8;
    int mspan  = Mb - mstart; if (mspan > 8) mspan = 8;
    int mb_id  = mstart + rem % mspan;
    int nb_id  = rem / mspan;
    const int m0 = mb_id * 128;
    const int n0 = nb_id * 128;

    // Global load: thread handles float4 columns c4 = tid&7 of rows r0+32i
    const int c4 = tid & 7;
    const int r0 = tid >> 3;
    const float* Abase = A + (size_t)(m0 + r0) * K + c4 * 4;
    const float* Bbase = B + (size_t)(n0 + r0) * K + c4 * 4;

    const int kb_s    = c4 >> 1;         // which k8 this thread's quad belongs to
    const int regA_hi = (c4 & 1) << 1;   // k-half bit of A reg index
    const int regB    = (c4 & 1);        // k-half = B reg index

    float4 ar[4], br[4];
    const int NT = K >> 5;

    // prologue load
    #pragma unroll
    for (int i = 0; i < 4; i++) {
        ar[i] = *(const float4*)(Abase + (size_t)(32 * i) * K);
        br[i] = *(const float4*)(Bbase + (size_t)(32 * i) * K);
    }
    #pragma unroll
    for (int i = 0; i < 4; i++) {
        int ml = r0 + 32 * i;
        int mb = ml >> 4;
        int lrow = (ml & 7) << 2;
        int regA = ((ml >> 3) & 1) | regA_hi;
        const float* av = (const float*)&ar[i];
        const float* bv = (const float*)&br[i];
        int nb = ml >> 3;
        #pragma unroll
        for (int u = 0; u < 4; u++) {
            As[kb_s][mb][lrow + u][regA] = f2tf32(av[u]);
            Bs[kb_s][nb][lrow + u][regB] = f2tf32(bv[u]);
        }
    }
    __syncthreads();

    float acc[2][8][4];
    #pragma unroll
    for (int i = 0; i < 2; i++)
        #pragma unroll
        for (int j = 0; j < 8; j++)
            #pragma unroll
            for (int r = 0; r < 4; r++) acc[i][j][r] = 0.f;

    for (int kt = 0; kt < NT; kt++) {
        if (kt + 1 < NT) {
            #pragma unroll
            for (int i = 0; i < 4; i++) {
                ar[i] = *(const float4*)(Abase + (size_t)(32 * i) * K + (kt + 1) * 32);
                br[i] = *(const float4*)(Bbase + (size_t)(32 * i) * K + (kt + 1) * 32);
            }
        }
        // compute on current smem tile
        #pragma unroll
        for (int kb = 0; kb < 4; kb++) {
            unsigned a[2][4], b[8][2];
            #pragma unroll
            for (int mb2 = 0; mb2 < 2; mb2++) {
                uint4 t4 = *(const uint4*)&As[kb][wr * 2 + mb2][lane][0];
                a[mb2][0] = t4.x; a[mb2][1] = t4.y; a[mb2][2] = t4.z; a[mb2][3] = t4.w;
            }
            #pragma unroll
            for (int nb2 = 0; nb2 < 8; nb2++) {
                uint2 t2 = *(const uint2*)&Bs[kb][wc * 8 + nb2][lane][0];
                b[nb2][0] = t2.x; b[nb2][1] = t2.y;
            }
            #pragma unroll
            for (int mb2 = 0; mb2 < 2; mb2++)
                #pragma unroll
                for (int nb2 = 0; nb2 < 8; nb2++)
                    mma_tf32(acc[mb2][nb2], a[mb2], b[nb2]);
        }
        __syncthreads();
        if (kt + 1 < NT) {
            #pragma unroll
            for (int i = 0; i < 4; i++) {
                int ml = r0 + 32 * i;
                int mb = ml >> 4;
                int lrow = (ml & 7) << 2;
                int regA = ((ml >> 3) & 1) | regA_hi;
                const float* av = (const float*)&ar[i];
                const float* bv = (const float*)&br[i];
                int nb = ml >> 3;
                #pragma unroll
                for (int u = 0; u < 4; u++) {
                    As[kb_s][mb][lrow + u][regA] = f2tf32(av[u]);
                    Bs[kb_s][nb][lrow + u][regB] = f2tf32(bv[u]);
                }
            }
            __syncthreads();
        }
    }

    // epilogue
    #pragma unroll
    for (int mb2 = 0; mb2 < 2; mb2++) {
        int row = m0 + (wr * 2 + mb2) * 16 + (lane >> 2);
        #pragma unroll
        for (int nb2 = 0; nb2 < 8; nb2++) {
            int col = n0 + (wc * 8 + nb2) * 8 + (lane & 3) * 2;
            float* cp = C + (size_t)row * N + col;
            *(float2*)cp = make_float2(acc[mb2][nb2][0], acc[mb2][nb2][1]);
            *(float2*)(cp + (size_t)8 * N) = make_float2(acc[mb2][nb2][2], acc[mb2][nb2][3]);
        }
    }
}

// ---------------------------------------------------------------------------
// RoPE, in-place on q and k halves of qkv
// ---------------------------------------------------------------------------
__global__ __launch_bounds__(256) void rope_kernel(
    float* __restrict__ qkv, const float* __restrict__ cs, const float* __restrict__ sn)
{
    int idx = blockIdx.x * 256 + threadIdx.x;      // over T*NHEAD*32
    int d = idx & 31;
    int h = (idx >> 5) & 15;
    int t = idx >> 9;
    float c = cs[t * ROT_H + d];
    float s = sn[t * ROT_H + d];
    float* qp = qkv + (size_t)t * QKV_W + h * HD;
    float x1 = qp[d], x2 = qp[32 + d];
    qp[d]      = x1 * c - x2 * s;
    qp[32 + d] = x2 * c + x1 * s;
    float* kp = qp + HIDDEN;
    x1 = kp[d]; x2 = kp[32 + d];
    kp[d]      = x1 * c - x2 * s;
    kp[32 + d] = x2 * c + x1 * s;
}

// ---------------------------------------------------------------------------
// fp32 flash attention, causal. 64x64 tiles, hd=256 fully resident in smem.
// grid = (16 q-tiles, 128 batch*head), 256 threads.
// Swizzled k/v/q smem (float4 granularity): phys = row*64 + (c4 ^ ((row>>2)&7))
// ---------------------------------------------------------------------------
#define ATTN_SMEM (3 * 4096 * 16 + 64 * 68 * 4 + 3 * 64 * 4)

__device__ __forceinline__ int sw_idx(int row, int c4) {
    return row * 64 + (c4 ^ ((row >> 2) & 7));
}

__global__ __launch_bounds__(256) void attn_kernel(
    const float* __restrict__ qkv, float* __restrict__ attn_out)
{
    extern __shared__ float4 sm4[];
    float4* q4 = sm4;            // 4096 float4
    float4* k4 = sm4 + 4096;
    float4* v4 = sm4 + 8192;
    float*  sp   = (float*)(sm4 + 12288);   // [64][68]
    float*  mrow = sp + 64 * 68;
    float*  lrow = mrow + 64;
    float*  arow = lrow + 64;

    const int tid = threadIdx.x;
    const int qt  = blockIdx.x;
    const int bh  = blockIdx.y;
    const int b   = bh >> 4;
    const int h   = bh & 15;
    const int t0  = b * SEQ + qt * 64;
    const float scale = 0.0625f;   // hd^-0.5

    const int ldc4 = tid & 63;     // float4 column for tile loads
    const int ldr0 = tid >> 6;     // base row (0..3), rows ldr0 + 4i

    // load q tile, pre-scaled
    #pragma unroll
    for (int i = 0; i < 16; i++) {
        int row = ldr0 + 4 * i;
        float4 qv = *(const float4*)(qkv + (size_t)(t0 + row) * QKV_W + h * HD + 4 * ldc4);
        qv.x *= scale; qv.y *= scale; qv.z *= scale; qv.w *= scale;
        q4[sw_idx(row, ldc4)] = qv;
    }
    if (tid < 64) { mrow[tid] = -INFINITY; lrow[tid] = 0.f; }

    const int i0 = (tid >> 4) << 2;   // 4 q-rows owned (score + pv phases)
    const int j0 = (tid & 15) << 2;   // 4 k-cols owned (score phase)
    const int c0 = (tid & 15) << 4;   // 16 hd-cols owned (pv phase)

    float o[4][16];
    #pragma unroll
    for (int ii = 0; ii < 4; ii++)
        #pragma unroll
        for (int cc = 0; cc < 16; cc++) o[ii][cc] = 0.f;

    for (int kt = 0; kt <= qt; kt++) {
        __syncthreads();   // prev pv done before overwriting k/v
        const int tk = b * SEQ + kt * 64;
        #pragma unroll
        for (int i = 0; i < 16; i++) {
            int row = ldr0 + 4 * i;
            const float* base = qkv + (size_t)(tk + row) * QKV_W + h * HD + 4 * ldc4;
            k4[sw_idx(row, ldc4)] = *(const float4*)(base + HIDDEN);
            v4[sw_idx(row, ldc4)] = *(const float4*)(base + 2 * HIDDEN);
        }
        __syncthreads();

        // ---- scores: s[i0..+3][j0..+3] = q . k ----
        float sacc[4][4];
        #pragma unroll
        for (int ii = 0; ii < 4; ii++)
            #pragma unroll
            for (int jj = 0; jj < 4; jj++) sacc[ii][jj] = 0.f;

        for (int cc4 = 0; cc4 < 64; cc4++) {
            float4 qv[4], kv[4];
            #pragma unroll
            for (int ii = 0; ii < 4; ii++) qv[ii] = q4[sw_idx(i0 + ii, cc4)];
            #pragma unroll
            for (int jj = 0; jj < 4; jj++) kv[jj] = k4[sw_idx(j0 + jj, cc4)];
            #pragma unroll
            for (int ii = 0; ii < 4; ii++)
                #pragma unroll
                for (int jj = 0; jj < 4; jj++)
                    sacc[ii][jj] += qv[ii].x * kv[jj].x + qv[ii].y * kv[jj].y
                                  + qv[ii].z * kv[jj].z + qv[ii].w * kv[jj].w;
        }
        if (kt == qt) {   // diagonal tile: causal mask
            #pragma unroll
            for (int ii = 0; ii < 4; ii++)
                #pragma unroll
                for (int jj = 0; jj < 4; jj++)
                    if (j0 + jj > i0 + ii) sacc[ii][jj] = -1e30f;
        }
        #pragma unroll
        for (int ii = 0; ii < 4; ii++)
            *(float4*)&sp[(i0 + ii) * 68 + j0] =
                make_float4(sacc[ii][0], sacc[ii][1], sacc[ii][2], sacc[ii][3]);
        __syncthreads();

        // ---- online softmax row pass: 4 threads per row ----
        {
            int row = tid >> 2, seg = tid & 3;
            float vals[16];
            float mx = -INFINITY;
            #pragma unroll
            for (int jj = 0; jj < 16; jj++) {
                vals[jj] = sp[row * 68 + seg * 16 + jj];
                mx = fmaxf(mx, vals[jj]);
            }
            mx = fmaxf(mx, __shfl_xor_sync(0xffffffffu, mx, 1));
            mx = fmaxf(mx, __shfl_xor_sync(0xffffffffu, mx, 2));
            float mo = mrow[row];
            float mn = fmaxf(mo, mx);
            float sum = 0.f;
            #pragma unroll
            for (int jj = 0; jj < 16; jj++) {
                float p = __expf(vals[jj] - mn);
                sp[row * 68 + seg * 16 + jj] = p;
                sum += p;
            }
            sum += __shfl_xor_sync(0xffffffffu, sum, 1);
            sum += __shfl_xor_sync(0xffffffffu, sum, 2);
            if (seg == 0) {
                float al = __expf(mo - mn);
                arow[row] = al;
                mrow[row] = mn;
                lrow[row] = lrow[row] * al + sum;
            }
        }
        __syncthreads();

        // ---- o = o*alpha + p @ v ----
        {
            float al[4];
            #pragma unroll
            for (int ii = 0; ii < 4; ii++) al[ii] = arow[i0 + ii];
            #pragma unroll
            for (int ii = 0; ii < 4; ii++)
                #pragma unroll
                for (int cc = 0; cc < 16; cc++) o[ii][cc] *= al[ii];

            for (int j = 0; j < 64; j++) {
                float pr[4];
                #pragma unroll
                for (int ii = 0; ii < 4; ii++) pr[ii] = sp[(i0 + ii) * 68 + j];
                float4 vv[4];
                #pragma unroll
                for (int u = 0; u < 4; u++) vv[u] = v4[sw_idx(j, (c0 >> 2) + u)];
                #pragma unroll
                for (int ii = 0; ii < 4; ii++) {
                    #pragma unroll
                    for (int u = 0; u < 4; u++) {
                        o[ii][4 * u + 0] += pr[ii] * vv[u].x;
                        o[ii][4 * u + 1] += pr[ii] * vv[u].y;
                        o[ii][4 * u + 2] += pr[ii] * vv[u].z;
                        o[ii][4 * u + 3] += pr[ii] * vv[u].w;
                    }
                }
            }
        }
    }

    // ---- normalize and store ----
    #pragma unroll
    for (int ii = 0; ii < 4; ii++) {
        float inv = 1.0f / lrow[i0 + ii];
        float* op = attn_out + (size_t)(t0 + i0 + ii) * HIDDEN + h * HD + c0;
        #pragma unroll
        for (int u = 0; u < 4; u++) {
            *(float4*)(op + 4 * u) = make_float4(
                o[ii][4 * u + 0] * inv, o[ii][4 * u + 1] * inv,
                o[ii][4 * u + 2] * inv, o[ii][4 * u + 3] * inv);
        }
    }
}

// ---------------------------------------------------------------------------
// launch
// ---------------------------------------------------------------------------
extern "C" void kernel_launch(void* const* d_in, const int* in_sizes, int n_in,
                              void* d_out, int out_size)
{
    const float* hidden = (const float*)d_in[0];
    const float* w_qkv  = (const float*)d_in[1];
    const float* w_o    = (const float*)d_in[2];
    const float* cosp   = (const float*)d_in[3];
    const float* sinp   = (const float*)d_in[4];
    // d_in[5..8] (caches, slots, batch_size) unused: cache write+gather is identity.

    float* qkv;  cudaGetSymbolAddress((void**)&qkv,  g_qkv);
    float* attn; cudaGetSymbolAddress((void**)&attn, g_attn);

    cudaFuncSetAttribute(attn_kernel, cudaFuncAttributeMaxDynamicSharedMemorySize, ATTN_SMEM);

    // 1) qkv = hidden @ w_qkv^T
    {
        dim3 grid(QKV_W / 128, T_TOK / 128);
        gemm_tf32_nt<<<grid, 256>>>(hidden, w_qkv, qkv, T_TOK, QKV_W, HIDDEN);
    }
    // 2) RoPE in place on q,k
    rope_kernel<<<(T_TOK * NHEAD * 32) / 256, 256>>>(qkv, cosp, sinp);
    // 3) attention -> attn scratch
    {
        dim3 grid(SEQ / 64, BATCH * NHEAD);
        attn_kernel<<<grid, 256, ATTN_SMEM>>>(qkv, attn);
    }
    // 4) out = attn @ w_o^T
    {
        dim3 grid(HIDDEN / 128, T_TOK / 128);
        gemm_tf32_nt<<<grid, 256>>>(attn, w_o, (float*)d_out, T_TOK, HIDDEN, HIDDEN);
    }
}

// round 3
// speedup vs baseline: 1.7035x; 1.7035x over previous
#include <cuda_runtime.h>
#include <cuda_bf16.h>
#include <math.h>
#include <stdint.h>

// ---------------------------------------------------------------------------
// Problem constants
// ---------------------------------------------------------------------------
#define T_TOK   8192
#define HIDDEN  4096
#define NHEAD   16
#define HD      256
#define QKV_W   (3 * HIDDEN)     // 12288
#define BATCH   8
#define SEQ     1024
#define ROT_H   32               // rotary_dim/2

// Scratch (device globals: allocation-free rule)
__device__ float g_qkv[(size_t)T_TOK * QKV_W];     // 8192 x 12288
__device__ float g_attn[(size_t)T_TOK * HIDDEN];   // 8192 x 4096

// ---------------------------------------------------------------------------
// helpers
// ---------------------------------------------------------------------------
__device__ __forceinline__ uint32_t smem_u32(const void* p) {
    uint32_t a;
    asm("{ .reg .u64 t; cvta.to.shared.u64 t, %1; cvt.u32.u64 %0, t; }"
        : "=r"(a) : "l"(p));
    return a;
}

__device__ __forceinline__ unsigned f2tf32(float x) {
    unsigned u;
    asm("cvt.rna.tf32.f32 %0, %1;" : "=r"(u) : "f"(x));
    return u;
}

__device__ __forceinline__ void mma_tf32(float* d, const unsigned* a, const unsigned* b) {
    asm volatile(
        "mma.sync.aligned.m16n8k8.row.col.f32.tf32.tf32.f32 "
        "{%0,%1,%2,%3}, {%4,%5,%6,%7}, {%8,%9}, {%0,%1,%2,%3};\n"
        : "+f"(d[0]), "+f"(d[1]), "+f"(d[2]), "+f"(d[3])
        : "r"(a[0]), "r"(a[1]), "r"(a[2]), "r"(a[3]),
          "r"(b[0]), "r"(b[1]));
}

__device__ __forceinline__ void cp16(uint32_t dst, const void* src) {
    asm volatile("cp.async.cg.shared.global [%0], [%1], 16;"
                 :: "r"(dst), "l"(src) : "memory");
}
#define CP_COMMIT()  asm volatile("cp.async.commit_group;" ::: "memory")
#define CP_WAIT2()   asm volatile("cp.async.wait_group 2;" ::: "memory")

// ---------------------------------------------------------------------------
// tf32 mma.sync GEMM (NT): C[M][N] = sum_k A[M][K] * B[N][K]
// CTA tile 128x256, warp tile 64x64 (8 warps, 2x4), K-stage 32,
// 3-stage cp.async pipeline, XOR-swizzled k-major smem, conflict-free LDS.32
// fragment loads, consumer-side cvt.rna (numerics identical to producer-side).
// ---------------------------------------------------------------------------
#define GTILE_M     128
#define GTILE_N     256
#define KTILE       32
#define A_STAGE_F   (GTILE_M * 32)          // 4096 floats (16 KB)
#define B_STAGE_F   (GTILE_N * 32)          // 8192 floats (32 KB)
#define STAGE_F     (A_STAGE_F + B_STAGE_F) // 12288 floats (48 KB)
#define NSTAGE      3
#define GEMM_SMEM   (NSTAGE * STAGE_F * 4)  // 147456 B

__global__ __launch_bounds__(256, 1) void gemm_tc(
    const float* __restrict__ A, const float* __restrict__ B,
    float* __restrict__ C, int M, int N, int K)
{
    extern __shared__ __align__(128) float smf[];
    const uint32_t sb = smem_u32(smf);

    const int tid  = threadIdx.x;
    const int lane = tid & 31;
    const int wid  = tid >> 5;
    const int wm   = wid >> 2;    // 0..1
    const int wn   = wid & 3;     // 0..3

    // CTA swizzle: groups of 8 m-tiles so weight panels stay L2-resident
    const int Nb = gridDim.x;
    const int Mb = gridDim.y;
    int linear = blockIdx.y * Nb + blockIdx.x;
    int group  = linear / (Nb * 8);
    int rem    = linear - group * (Nb * 8);
    int mstart = group * 8;
    int mspan  = Mb - mstart; if (mspan > 8) mspan = 8;
    int mb_id  = mstart + rem % mspan;
    int nb_id  = rem / mspan;
    const int m0 = mb_id * GTILE_M;
    const int n0 = nb_id * GTILE_N;

    // cp.async source pointers + swizzled smem byte offsets.
    // A stage: 1024 float4 -> 4/thread. B stage: 2048 float4 -> 8/thread.
    const float* srcA[4];  uint32_t dstA[4];
    const float* srcB[8];  uint32_t dstB[8];
    #pragma unroll
    for (int i = 0; i < 4; i++) {
        int idx = tid + 256 * i;
        int row = idx >> 3, c4 = idx & 7;
        srcA[i] = A + (size_t)(m0 + row) * K + c4 * 4;
        dstA[i] = (uint32_t)((row * 8 + (c4 ^ (row & 7))) * 16);
    }
    #pragma unroll
    for (int i = 0; i < 8; i++) {
        int idx = tid + 256 * i;
        int row = idx >> 3, c4 = idx & 7;
        srcB[i] = B + (size_t)(n0 + row) * K + c4 * 4;
        dstB[i] = (uint32_t)(A_STAGE_F * 4 + (row * 8 + (c4 ^ (row & 7))) * 16);
    }

    const int NT = K >> 5;

    // prologue: fill 3 stages
    #pragma unroll
    for (int s = 0; s < NSTAGE; s++) {
        const uint32_t st = sb + s * (STAGE_F * 4);
        #pragma unroll
        for (int i = 0; i < 4; i++) cp16(st + dstA[i], srcA[i] + s * KTILE);
        #pragma unroll
        for (int i = 0; i < 8; i++) cp16(st + dstB[i], srcB[i] + s * KTILE);
        CP_COMMIT();
    }

    float acc[4][8][4];
    #pragma unroll
    for (int f = 0; f < 4; f++)
        #pragma unroll
        for (int g = 0; g < 8; g++)
            #pragma unroll
            for (int r = 0; r < 4; r++) acc[f][g][r] = 0.f;

    const int r   = lane >> 2;     // 0..7
    const int c   = lane & 3;      // 0..3
    const int szx = r << 2;        // XOR swizzle for this lane's rows
    const int aRowBase = wm * 64 + r;
    const int bRowBase = wn * 64 + r;

    for (int kt = 0; kt < NT; kt++) {
        CP_WAIT2();
        __syncthreads();

        const float* sA = smf + (kt % 3) * STAGE_F;
        const float* sB = sA + A_STAGE_F;

        #pragma unroll
        for (int kb = 0; kb < 4; kb++) {
            const int col0 = (kb * 8 + c) ^ szx;
            const int col1 = col0 ^ 4;

            unsigned af[4][4];
            #pragma unroll
            for (int f = 0; f < 4; f++) {
                int base = (aRowBase + f * 16) * 32;
                af[f][0] = f2tf32(sA[base + col0]);
                af[f][1] = f2tf32(sA[base + 256 + col0]);   // +8 rows
                af[f][2] = f2tf32(sA[base + col1]);
                af[f][3] = f2tf32(sA[base + 256 + col1]);
            }
            unsigned bf[8][2];
            #pragma unroll
            for (int g = 0; g < 8; g++) {
                int base = (bRowBase + g * 8) * 32;
                bf[g][0] = f2tf32(sB[base + col0]);
                bf[g][1] = f2tf32(sB[base + col1]);
            }
            #pragma unroll
            for (int f = 0; f < 4; f++)
                #pragma unroll
                for (int g = 0; g < 8; g++)
                    mma_tf32(acc[f][g], af[f], bf[g]);
        }
        __syncthreads();

        if (kt + NSTAGE < NT) {
            const uint32_t st = sb + (kt % 3) * (STAGE_F * 4);
            const int ko = (kt + NSTAGE) * KTILE;
            #pragma unroll
            for (int i = 0; i < 4; i++) cp16(st + dstA[i], srcA[i] + ko);
            #pragma unroll
            for (int i = 0; i < 8; i++) cp16(st + dstB[i], srcB[i] + ko);
        }
        CP_COMMIT();
    }

    // epilogue
    #pragma unroll
    for (int f = 0; f < 4; f++) {
        int row = m0 + wm * 64 + f * 16 + r;
        #pragma unroll
        for (int g = 0; g < 8; g++) {
            int col = n0 + wn * 64 + g * 8 + c * 2;
            float* cp = C + (size_t)row * N + col;
            *(float2*)cp = make_float2(acc[f][g][0], acc[f][g][1]);
            *(float2*)(cp + (size_t)8 * N) = make_float2(acc[f][g][2], acc[f][g][3]);
        }
    }
}

// ---------------------------------------------------------------------------
// RoPE, in-place on q and k halves of qkv
// ---------------------------------------------------------------------------
__global__ __launch_bounds__(256) void rope_kernel(
    float* __restrict__ qkv, const float* __restrict__ cs, const float* __restrict__ sn)
{
    int idx = blockIdx.x * 256 + threadIdx.x;      // over T*NHEAD*32
    int d = idx & 31;
    int h = (idx >> 5) & 15;
    int t = idx >> 9;
    float c = cs[t * ROT_H + d];
    float s = sn[t * ROT_H + d];
    float* qp = qkv + (size_t)t * QKV_W + h * HD;
    float x1 = qp[d], x2 = qp[32 + d];
    qp[d]      = x1 * c - x2 * s;
    qp[32 + d] = x2 * c + x1 * s;
    float* kp = qp + HIDDEN;
    x1 = kp[d]; x2 = kp[32 + d];
    kp[d]      = x1 * c - x2 * s;
    kp[32 + d] = x2 * c + x1 * s;
}

// ---------------------------------------------------------------------------
// fp32 flash attention, causal. 64x64 tiles, hd=256 fully resident in smem.
// grid = (16 q-tiles, 128 batch*head), 256 threads.
// ---------------------------------------------------------------------------
#define ATTN_SMEM (3 * 4096 * 16 + 64 * 68 * 4 + 3 * 64 * 4)

__device__ __forceinline__ int sw_idx(int row, int c4) {
    return row * 64 + (c4 ^ ((row >> 2) & 7));
}

__global__ __launch_bounds__(256) void attn_kernel(
    const float* __restrict__ qkv, float* __restrict__ attn_out)
{
    extern __shared__ float4 sm4[];
    float4* q4 = sm4;            // 4096 float4
    float4* k4 = sm4 + 4096;
    float4* v4 = sm4 + 8192;
    float*  sp   = (float*)(sm4 + 12288);   // [64][68]
    float*  mrow = sp + 64 * 68;
    float*  lrow = mrow + 64;
    float*  arow = lrow + 64;

    const int tid = threadIdx.x;
    const int qt  = blockIdx.x;
    const int bh  = blockIdx.y;
    const int b   = bh >> 4;
    const int h   = bh & 15;
    const int t0  = b * SEQ + qt * 64;
    const float scale = 0.0625f;   // hd^-0.5

    const int ldc4 = tid & 63;
    const int ldr0 = tid >> 6;

    #pragma unroll
    for (int i = 0; i < 16; i++) {
        int row = ldr0 + 4 * i;
        float4 qv = *(const float4*)(qkv + (size_t)(t0 + row) * QKV_W + h * HD + 4 * ldc4);
        qv.x *= scale; qv.y *= scale; qv.z *= scale; qv.w *= scale;
        q4[sw_idx(row, ldc4)] = qv;
    }
    if (tid < 64) { mrow[tid] = -INFINITY; lrow[tid] = 0.f; }

    const int i0 = (tid >> 4) << 2;
    const int j0 = (tid & 15) << 2;
    const int c0 = (tid & 15) << 4;

    float o[4][16];
    #pragma unroll
    for (int ii = 0; ii < 4; ii++)
        #pragma unroll
        for (int cc = 0; cc < 16; cc++) o[ii][cc] = 0.f;

    for (int kt = 0; kt <= qt; kt++) {
        __syncthreads();
        const int tk = b * SEQ + kt * 64;
        #pragma unroll
        for (int i = 0; i < 16; i++) {
            int row = ldr0 + 4 * i;
            const float* base = qkv + (size_t)(tk + row) * QKV_W + h * HD + 4 * ldc4;
            k4[sw_idx(row, ldc4)] = *(const float4*)(base + HIDDEN);
            v4[sw_idx(row, ldc4)] = *(const float4*)(base + 2 * HIDDEN);
        }
        __syncthreads();

        float sacc[4][4];
        #pragma unroll
        for (int ii = 0; ii < 4; ii++)
            #pragma unroll
            for (int jj = 0; jj < 4; jj++) sacc[ii][jj] = 0.f;

        for (int cc4 = 0; cc4 < 64; cc4++) {
            float4 qv[4], kv[4];
            #pragma unroll
            for (int ii = 0; ii < 4; ii++) qv[ii] = q4[sw_idx(i0 + ii, cc4)];
            #pragma unroll
            for (int jj = 0; jj < 4; jj++) kv[jj] = k4[sw_idx(j0 + jj, cc4)];
            #pragma unroll
            for (int ii = 0; ii < 4; ii++)
                #pragma unroll
                for (int jj = 0; jj < 4; jj++)
                    sacc[ii][jj] += qv[ii].x * kv[jj].x + qv[ii].y * kv[jj].y
                                  + qv[ii].z * kv[jj].z + qv[ii].w * kv[jj].w;
        }
        if (kt == qt) {
            #pragma unroll
            for (int ii = 0; ii < 4; ii++)
                #pragma unroll
                for (int jj = 0; jj < 4; jj++)
                    if (j0 + jj > i0 + ii) sacc[ii][jj] = -1e30f;
        }
        #pragma unroll
        for (int ii = 0; ii < 4; ii++)
            *(float4*)&sp[(i0 + ii) * 68 + j0] =
                make_float4(sacc[ii][0], sacc[ii][1], sacc[ii][2], sacc[ii][3]);
        __syncthreads();

        {
            int row = tid >> 2, seg = tid & 3;
            float vals[16];
            float mx = -INFINITY;
            #pragma unroll
            for (int jj = 0; jj < 16; jj++) {
                vals[jj] = sp[row * 68 + seg * 16 + jj];
                mx = fmaxf(mx, vals[jj]);
            }
            mx = fmaxf(mx, __shfl_xor_sync(0xffffffffu, mx, 1));
            mx = fmaxf(mx, __shfl_xor_sync(0xffffffffu, mx, 2));
            float mo = mrow[row];
            float mn = fmaxf(mo, mx);
            float sum = 0.f;
            #pragma unroll
            for (int jj = 0; jj < 16; jj++) {
                float p = __expf(vals[jj] - mn);
                sp[row * 68 + seg * 16 + jj] = p;
                sum += p;
            }
            sum += __shfl_xor_sync(0xffffffffu, sum, 1);
            sum += __shfl_xor_sync(0xffffffffu, sum, 2);
            if (seg == 0) {
                float al = __expf(mo - mn);
                arow[row] = al;
                mrow[row] = mn;
                lrow[row] = lrow[row] * al + sum;
            }
        }
        __syncthreads();

        {
            float al[4];
            #pragma unroll
            for (int ii = 0; ii < 4; ii++) al[ii] = arow[i0 + ii];
            #pragma unroll
            for (int ii = 0; ii < 4; ii++)
                #pragma unroll
                for (int cc = 0; cc < 16; cc++) o[ii][cc] *= al[ii];

            for (int j = 0; j < 64; j++) {
                float pr[4];
                #pragma unroll
                for (int ii = 0; ii < 4; ii++) pr[ii] = sp[(i0 + ii) * 68 + j];
                float4 vv[4];
                #pragma unroll
                for (int u = 0; u < 4; u++) vv[u] = v4[sw_idx(j, (c0 >> 2) + u)];
                #pragma unroll
                for (int ii = 0; ii < 4; ii++) {
                    #pragma unroll
                    for (int u = 0; u < 4; u++) {
                        o[ii][4 * u + 0] += pr[ii] * vv[u].x;
                        o[ii][4 * u + 1] += pr[ii] * vv[u].y;
                        o[ii][4 * u + 2] += pr[ii] * vv[u].z;
                        o[ii][4 * u + 3] += pr[ii] * vv[u].w;
                    }
                }
            }
        }
    }

    #pragma unroll
    for (int ii = 0; ii < 4; ii++) {
        float inv = 1.0f / lrow[i0 + ii];
        float* op = attn_out + (size_t)(t0 + i0 + ii) * HIDDEN + h * HD + c0;
        #pragma unroll
        for (int u = 0; u < 4; u++) {
            *(float4*)(op + 4 * u) = make_float4(
                o[ii][4 * u + 0] * inv, o[ii][4 * u + 1] * inv,
                o[ii][4 * u + 2] * inv, o[ii][4 * u + 3] * inv);
        }
    }
}

// ---------------------------------------------------------------------------
// launch
// ---------------------------------------------------------------------------
extern "C" void kernel_launch(void* const* d_in, const int* in_sizes, int n_in,
                              void* d_out, int out_size)
{
    const float* hidden = (const float*)d_in[0];
    const float* w_qkv  = (const float*)d_in[1];
    const float* w_o    = (const float*)d_in[2];
    const float* cosp   = (const float*)d_in[3];
    const float* sinp   = (const float*)d_in[4];
    // d_in[5..8] (caches, slots, batch_size) unused: cache write+gather is identity.

    float* qkv;  cudaGetSymbolAddress((void**)&qkv,  g_qkv);
    float* attn; cudaGetSymbolAddress((void**)&attn, g_attn);

    cudaFuncSetAttribute(gemm_tc, cudaFuncAttributeMaxDynamicSharedMemorySize, GEMM_SMEM);
    cudaFuncSetAttribute(attn_kernel, cudaFuncAttributeMaxDynamicSharedMemorySize, ATTN_SMEM);

    // 1) qkv = hidden @ w_qkv^T   (tf32 mma.sync, cp.async pipeline)
    {
        dim3 grid(QKV_W / GTILE_N, T_TOK / GTILE_M);   // (48, 64)
        gemm_tc<<<grid, 256, GEMM_SMEM>>>(hidden, w_qkv, qkv, T_TOK, QKV_W, HIDDEN);
    }
    // 2) RoPE in place on q,k
    rope_kernel<<<(T_TOK * NHEAD * 32) / 256, 256>>>(qkv, cosp, sinp);
    // 3) attention -> attn scratch
    {
        dim3 grid(SEQ / 64, BATCH * NHEAD);
        attn_kernel<<<grid, 256, ATTN_SMEM>>>(qkv, attn);
    }
    // 4) out = attn @ w_o^T   (tf32 mma.sync, cp.async pipeline)
    {
        dim3 grid(HIDDEN / GTILE_N, T_TOK / GTILE_M);  // (16, 64)
        gemm_tc<<<grid, 256, GEMM_SMEM>>>(attn, w_o, (float*)d_out, T_TOK, HIDDEN, HIDDEN);
    }
}

// round 4
// speedup vs baseline: 2.2907x; 1.3447x over previous
#include <cuda_runtime.h>
#include <cuda_bf16.h>
#include <math.h>
#include <stdint.h>

// ---------------------------------------------------------------------------
// Problem constants
// ---------------------------------------------------------------------------
#define T_TOK   8192
#define HIDDEN  4096
#define NHEAD   16
#define HD      256
#define QKV_W   (3 * HIDDEN)     // 12288
#define BATCH   8
#define SEQ     1024
#define ROT_H   32               // rotary_dim/2

// Scratch (device globals: allocation-free rule)
__device__ float g_qkv[(size_t)T_TOK * QKV_W];     // 8192 x 12288
__device__ float g_attn[(size_t)T_TOK * HIDDEN];   // 8192 x 4096 (tf32-rounded)
__device__ float g_hid[(size_t)T_TOK * HIDDEN];    // rounded hidden
__device__ float g_wq [(size_t)QKV_W * HIDDEN];    // rounded w_qkv
__device__ float g_wo [(size_t)HIDDEN * HIDDEN];   // rounded w_o

// ---------------------------------------------------------------------------
// helpers
// ---------------------------------------------------------------------------
__device__ __forceinline__ uint32_t smem_u32(const void* p) {
    uint32_t a;
    asm("{ .reg .u64 t; cvta.to.shared.u64 t, %1; cvt.u32.u64 %0, t; }"
        : "=r"(a) : "l"(p));
    return a;
}

__device__ __forceinline__ unsigned f2tf32(float x) {
    unsigned u;
    asm("cvt.rna.tf32.f32 %0, %1;" : "=r"(u) : "f"(x));
    return u;
}

__device__ __forceinline__ void mma_tf32(float* d, const unsigned* a, const unsigned* b) {
    asm volatile(
        "mma.sync.aligned.m16n8k8.row.col.f32.tf32.tf32.f32 "
        "{%0,%1,%2,%3}, {%4,%5,%6,%7}, {%8,%9}, {%0,%1,%2,%3};\n"
        : "+f"(d[0]), "+f"(d[1]), "+f"(d[2]), "+f"(d[3])
        : "r"(a[0]), "r"(a[1]), "r"(a[2]), "r"(a[3]),
          "r"(b[0]), "r"(b[1]));
}

__device__ __forceinline__ void cp16(uint32_t dst, const void* src) {
    asm volatile("cp.async.cg.shared.global [%0], [%1], 16;"
                 :: "r"(dst), "l"(src) : "memory");
}
#define CP_COMMIT()  asm volatile("cp.async.commit_group;" ::: "memory")
#define CP_WAIT2()   asm volatile("cp.async.wait_group 2;" ::: "memory")
#define CP_WAIT0()   asm volatile("cp.async.wait_group 0;" ::: "memory")

// ---------------------------------------------------------------------------
// tf32 rounding pre-pass (rna) — makes GEMM inputs cvt-free
// ---------------------------------------------------------------------------
__global__ __launch_bounds__(256) void round_tf32(
    float* __restrict__ dst, const float* __restrict__ src)
{
    size_t i = (size_t)(blockIdx.x * 256 + threadIdx.x) * 4;
    float4 v = *(const float4*)(src + i);
    v.x = __uint_as_float(f2tf32(v.x));
    v.y = __uint_as_float(f2tf32(v.y));
    v.z = __uint_as_float(f2tf32(v.z));
    v.w = __uint_as_float(f2tf32(v.w));
    *(float4*)(dst + i) = v;
}

// ---------------------------------------------------------------------------
// tf32 mma.sync GEMM (NT), inputs pre-rounded: C[M][N] = sum_k A[M][K]*B[N][K]
// CTA 128x256, warp tile 64x64 (2x4 warps), 3-stage cp.async, XOR swizzle.
// ---------------------------------------------------------------------------
#define GTILE_M     128
#define GTILE_N     256
#define KTILE       32
#define A_STAGE_F   (GTILE_M * 32)
#define B_STAGE_F   (GTILE_N * 32)
#define STAGE_F     (A_STAGE_F + B_STAGE_F)
#define NSTAGE      3
#define GEMM_SMEM   (NSTAGE * STAGE_F * 4)

__global__ __launch_bounds__(256, 1) void gemm_tc(
    const float* __restrict__ A, const float* __restrict__ B,
    float* __restrict__ C, int M, int N, int K)
{
    extern __shared__ __align__(128) float smf[];
    const uint32_t sb = smem_u32(smf);

    const int tid  = threadIdx.x;
    const int lane = tid & 31;
    const int wid  = tid >> 5;
    const int wm   = wid >> 2;
    const int wn   = wid & 3;

    const int Nb = gridDim.x;
    const int Mb = gridDim.y;
    int linear = blockIdx.y * Nb + blockIdx.x;
    int group  = linear / (Nb * 8);
    int rem    = linear - group * (Nb * 8);
    int mstart = group * 8;
    int mspan  = Mb - mstart; if (mspan > 8) mspan = 8;
    int mb_id  = mstart + rem % mspan;
    int nb_id  = rem / mspan;
    const int m0 = mb_id * GTILE_M;
    const int n0 = nb_id * GTILE_N;

    const float* srcA[4];  uint32_t dstA[4];
    const float* srcB[8];  uint32_t dstB[8];
    #pragma unroll
    for (int i = 0; i < 4; i++) {
        int idx = tid + 256 * i;
        int row = idx >> 3, c4 = idx & 7;
        srcA[i] = A + (size_t)(m0 + row) * K + c4 * 4;
        dstA[i] = (uint32_t)((row * 8 + (c4 ^ (row & 7))) * 16);
    }
    #pragma unroll
    for (int i = 0; i < 8; i++) {
        int idx = tid + 256 * i;
        int row = idx >> 3, c4 = idx & 7;
        srcB[i] = B + (size_t)(n0 + row) * K + c4 * 4;
        dstB[i] = (uint32_t)(A_STAGE_F * 4 + (row * 8 + (c4 ^ (row & 7))) * 16);
    }

    const int NT = K >> 5;

    #pragma unroll
    for (int s = 0; s < NSTAGE; s++) {
        const uint32_t st = sb + s * (STAGE_F * 4);
        #pragma unroll
        for (int i = 0; i < 4; i++) cp16(st + dstA[i], srcA[i] + s * KTILE);
        #pragma unroll
        for (int i = 0; i < 8; i++) cp16(st + dstB[i], srcB[i] + s * KTILE);
        CP_COMMIT();
    }

    float acc[4][8][4];
    #pragma unroll
    for (int f = 0; f < 4; f++)
        #pragma unroll
        for (int g = 0; g < 8; g++)
            #pragma unroll
            for (int r = 0; r < 4; r++) acc[f][g][r] = 0.f;

    const int r   = lane >> 2;
    const int c   = lane & 3;
    const int szx = r << 2;
    const int aRowBase = wm * 64 + r;
    const int bRowBase = wn * 64 + r;

    for (int kt = 0; kt < NT; kt++) {
        CP_WAIT2();
        __syncthreads();

        const float* sA = smf + (kt % 3) * STAGE_F;
        const float* sB = sA + A_STAGE_F;

        #pragma unroll
        for (int kb = 0; kb < 4; kb++) {
            const int col0 = (kb * 8 + c) ^ szx;
            const int col1 = col0 ^ 4;

            unsigned af[4][4];
            #pragma unroll
            for (int f = 0; f < 4; f++) {
                int base = (aRowBase + f * 16) * 32;
                af[f][0] = __float_as_uint(sA[base + col0]);
                af[f][1] = __float_as_uint(sA[base + 256 + col0]);
                af[f][2] = __float_as_uint(sA[base + col1]);
                af[f][3] = __float_as_uint(sA[base + 256 + col1]);
            }
            unsigned bf[8][2];
            #pragma unroll
            for (int g = 0; g < 8; g++) {
                int base = (bRowBase + g * 8) * 32;
                bf[g][0] = __float_as_uint(sB[base + col0]);
                bf[g][1] = __float_as_uint(sB[base + col1]);
            }
            #pragma unroll
            for (int f = 0; f < 4; f++)
                #pragma unroll
                for (int g = 0; g < 8; g++)
                    mma_tf32(acc[f][g], af[f], bf[g]);
        }
        __syncthreads();

        if (kt + NSTAGE < NT) {
            const uint32_t st = sb + (kt % 3) * (STAGE_F * 4);
            const int ko = (kt + NSTAGE) * KTILE;
            #pragma unroll
            for (int i = 0; i < 4; i++) cp16(st + dstA[i], srcA[i] + ko);
            #pragma unroll
            for (int i = 0; i < 8; i++) cp16(st + dstB[i], srcB[i] + ko);
        }
        CP_COMMIT();
    }

    #pragma unroll
    for (int f = 0; f < 4; f++) {
        int row = m0 + wm * 64 + f * 16 + r;
        #pragma unroll
        for (int g = 0; g < 8; g++) {
            int col = n0 + wn * 64 + g * 8 + c * 2;
            float* cp = C + (size_t)row * N + col;
            *(float2*)cp = make_float2(acc[f][g][0], acc[f][g][1]);
            *(float2*)(cp + (size_t)8 * N) = make_float2(acc[f][g][2], acc[f][g][3]);
        }
    }
}

// ---------------------------------------------------------------------------
// RoPE, in-place on q and k halves of qkv
// ---------------------------------------------------------------------------
__global__ __launch_bounds__(256) void rope_kernel(
    float* __restrict__ qkv, const float* __restrict__ cs, const float* __restrict__ sn)
{
    int idx = blockIdx.x * 256 + threadIdx.x;
    int d = idx & 31;
    int h = (idx >> 5) & 15;
    int t = idx >> 9;
    float c = cs[t * ROT_H + d];
    float s = sn[t * ROT_H + d];
    float* qp = qkv + (size_t)t * QKV_W + h * HD;
    float x1 = qp[d], x2 = qp[32 + d];
    qp[d]      = x1 * c - x2 * s;
    qp[32 + d] = x2 * c + x1 * s;
    float* kp = qp + HIDDEN;
    x1 = kp[d]; x2 = kp[32 + d];
    kp[d]      = x1 * c - x2 * s;
    kp[32 + d] = x2 * c + x1 * s;
}

// ---------------------------------------------------------------------------
// Tensor-core flash attention (3x-tf32 compensated, causal).
// CTA: 64 q-rows x one (b,h); k-tiles of 32. 8 warps: QK = 4q x 2k-halves,
// PV = 4q x 2d-halves. q pre-split hi/lo in smem; k raw (split on the fly);
// v split at load; p split at store, aliased onto dead k region.
// ---------------------------------------------------------------------------
#define AQ 64
#define AKT 32
// smem float offsets
#define S_QH 0                      // 64*256
#define S_QL 16384
#define S_KR 32768                  // 32*256 raw k (swizzled); aliases below
#define S_PH (S_KR + 0)             // 64*36
#define S_PL (S_KR + 2304)
#define S_PM (S_KR + 4608)          // 2*64 partial max
#define S_PS (S_KR + 4736)          // 2*64 partial sum
#define S_VH 40960                  // 32*264
#define S_VL 49408
#define S_M  57856                  // 64
#define S_L  57920                  // 64
#define ATT_SMEM   (57984 * 4)      // 231936 B

__global__ __launch_bounds__(256, 1) void attn_tc(
    const float* __restrict__ qkv, float* __restrict__ outp)
{
    extern __shared__ float sf[];
    const uint32_t sb = smem_u32(sf);
    const int tid = threadIdx.x, lane = tid & 31, w = tid >> 5;
    const int qt = 15 - blockIdx.x;                 // big tiles first
    const int bh = blockIdx.y;
    const int b = bh >> 4, h = bh & 15;
    const int t0 = b * SEQ + qt * AQ;
    const int wq = w & 3, wk = w >> 2;              // wk doubles as wd for PV
    const int cL = lane & 3;
    const int rL = lane >> 2;                       // 0..7
    const int rA = wq * 16 + rL;                    // owned q row (and +8)

    // ---- load q tile: scale (exact pow2), split hi/lo, swizzled store ----
    #pragma unroll
    for (int i = 0; i < 16; i++) {
        int idx = tid + 256 * i;
        int row = idx >> 6, c4 = idx & 63;
        float4 qv = *(const float4*)(qkv + (size_t)(t0 + row) * QKV_W + h * HD + c4 * 4);
        qv.x *= 0.0625f; qv.y *= 0.0625f; qv.z *= 0.0625f; qv.w *= 0.0625f;
        unsigned h0 = f2tf32(qv.x), h1 = f2tf32(qv.y), h2 = f2tf32(qv.z), h3 = f2tf32(qv.w);
        unsigned l0 = f2tf32(qv.x - __uint_as_float(h0));
        unsigned l1 = f2tf32(qv.y - __uint_as_float(h1));
        unsigned l2 = f2tf32(qv.z - __uint_as_float(h2));
        unsigned l3 = f2tf32(qv.w - __uint_as_float(h3));
        int off = row * 256 + ((c4 ^ (row & 7)) << 2);
        *(float4*)&sf[S_QH + off] = make_float4(__uint_as_float(h0), __uint_as_float(h1),
                                                __uint_as_float(h2), __uint_as_float(h3));
        *(float4*)&sf[S_QL + off] = make_float4(__uint_as_float(l0), __uint_as_float(l1),
                                                __uint_as_float(l2), __uint_as_float(l3));
    }
    if (tid < 64) { sf[S_M + tid] = -INFINITY; sf[S_L + tid] = 0.f; }

    float o[16][4];
    #pragma unroll
    for (int g = 0; g < 16; g++)
        #pragma unroll
        for (int r = 0; r < 4; r++) o[g][r] = 0.f;

    const int ktmax = 2 * qt + 1;

    for (int kt = 0; kt <= ktmax; kt++) {
        __syncthreads();    // p/v consumers done; q store done (iter 0)
        const int tk = b * SEQ + kt * AKT;
        // k: cp.async into swizzled raw tile
        #pragma unroll
        for (int i = 0; i < 8; i++) {
            int idx = tid + 256 * i;
            int row = idx >> 6, c4 = idx & 63;
            const float* src = qkv + (size_t)(tk + row) * QKV_W + HIDDEN + h * HD + c4 * 4;
            cp16(sb + (S_KR + row * 256 + ((c4 ^ (row & 7)) << 2)) * 4, src);
        }
        CP_COMMIT();
        // v: load raw, split hi/lo, padded store (stride 264)
        #pragma unroll
        for (int i = 0; i < 8; i++) {
            int idx = tid + 256 * i;
            int row = idx >> 6, c4 = idx & 63;
            float4 vv = *(const float4*)(qkv + (size_t)(tk + row) * QKV_W + 2 * HIDDEN + h * HD + c4 * 4);
            unsigned h0 = f2tf32(vv.x), h1 = f2tf32(vv.y), h2 = f2tf32(vv.z), h3 = f2tf32(vv.w);
            unsigned l0 = f2tf32(vv.x - __uint_as_float(h0));
            unsigned l1 = f2tf32(vv.y - __uint_as_float(h1));
            unsigned l2 = f2tf32(vv.z - __uint_as_float(h2));
            unsigned l3 = f2tf32(vv.w - __uint_as_float(h3));
            int off = row * 264 + c4 * 4;
            *(float4*)&sf[S_VH + off] = make_float4(__uint_as_float(h0), __uint_as_float(h1),
                                                    __uint_as_float(h2), __uint_as_float(h3));
            *(float4*)&sf[S_VL + off] = make_float4(__uint_as_float(l0), __uint_as_float(l1),
                                                    __uint_as_float(l2), __uint_as_float(l3));
        }
        CP_WAIT0();
        __syncthreads();

        // ---- QK: sacc[g][4] over 32 k8-blocks, 3-pass tf32 ----
        float sacc[2][4];
        #pragma unroll
        for (int g = 0; g < 2; g++)
            #pragma unroll
            for (int r = 0; r < 4; r++) sacc[g][r] = 0.f;

        #pragma unroll
        for (int kb = 0; kb < 32; kb++) {
            const int c4x = (2 * kb) ^ rL;
            const int a0 = rA * 256 + (c4x << 2) + cL;
            const int a2 = rA * 256 + ((c4x ^ 1) << 2) + cL;
            unsigned ah[4], al[4];
            ah[0] = __float_as_uint(sf[S_QH + a0]);
            ah[1] = __float_as_uint(sf[S_QH + a0 + 2048]);
            ah[2] = __float_as_uint(sf[S_QH + a2]);
            ah[3] = __float_as_uint(sf[S_QH + a2 + 2048]);
            al[0] = __float_as_uint(sf[S_QL + a0]);
            al[1] = __float_as_uint(sf[S_QL + a0 + 2048]);
            al[2] = __float_as_uint(sf[S_QL + a2]);
            al[3] = __float_as_uint(sf[S_QL + a2 + 2048]);
            #pragma unroll
            for (int g = 0; g < 2; g++) {
                int kbase = S_KR + (wk * 16 + g * 8 + rL) * 256;
                float r0 = sf[kbase + (c4x << 2) + cL];
                float r1 = sf[kbase + ((c4x ^ 1) << 2) + cL];
                unsigned bh[2], bl[2];
                bh[0] = f2tf32(r0); bl[0] = f2tf32(r0 - __uint_as_float(bh[0]));
                bh[1] = f2tf32(r1); bl[1] = f2tf32(r1 - __uint_as_float(bh[1]));
                mma_tf32(sacc[g], ah, bh);
                mma_tf32(sacc[g], al, bh);
                mma_tf32(sacc[g], ah, bl);
            }
        }

        // causal mask (only tiles touching the diagonal)
        if (kt >= 2 * qt) {
            #pragma unroll
            for (int g = 0; g < 2; g++)
                #pragma unroll
                for (int r = 0; r < 4; r++) {
                    int col = kt * AKT + wk * 16 + g * 8 + 2 * cL + (r & 1);
                    int row = qt * AQ + rA + 8 * (r >> 1);
                    if (col > row) sacc[g][r] = -1e30f;
                }
        }
        __syncthreads();    // all QK smem reads done; kr region reusable

        // ---- partial row max over this warp's 16 cols ----
        float mx0 = fmaxf(fmaxf(sacc[0][0], sacc[0][1]), fmaxf(sacc[1][0], sacc[1][1]));
        float mx1 = fmaxf(fmaxf(sacc[0][2], sacc[0][3]), fmaxf(sacc[1][2], sacc[1][3]));
        mx0 = fmaxf(mx0, __shfl_xor_sync(0xffffffffu, mx0, 1));
        mx0 = fmaxf(mx0, __shfl_xor_sync(0xffffffffu, mx0, 2));
        mx1 = fmaxf(mx1, __shfl_xor_sync(0xffffffffu, mx1, 1));
        mx1 = fmaxf(mx1, __shfl_xor_sync(0xffffffffu, mx1, 2));
        if (cL == 0) {
            sf[S_PM + wk * 64 + rA]     = mx0;
            sf[S_PM + wk * 64 + rA + 8] = mx1;
        }
        __syncthreads();

        // ---- stats + p = exp(s - m_new), split, store; o-scale ----
        float mo0 = sf[S_M + rA], mo1 = sf[S_M + rA + 8];
        float mn0 = fmaxf(mo0, fmaxf(sf[S_PM + rA],     sf[S_PM + 64 + rA]));
        float mn1 = fmaxf(mo1, fmaxf(sf[S_PM + rA + 8], sf[S_PM + 64 + rA + 8]));
        float al0 = __expf(mo0 - mn0), al1 = __expf(mo1 - mn1);

        float sum0 = 0.f, sum1 = 0.f;
        #pragma unroll
        for (int g = 0; g < 2; g++) {
            float p0 = __expf(sacc[g][0] - mn0);
            float p1 = __expf(sacc[g][1] - mn0);
            float p2 = __expf(sacc[g][2] - mn1);
            float p3 = __expf(sacc[g][3] - mn1);
            sum0 += p0 + p1; sum1 += p2 + p3;
            unsigned h0 = f2tf32(p0), h1 = f2tf32(p1), h2 = f2tf32(p2), h3 = f2tf32(p3);
            unsigned u0 = f2tf32(p0 - __uint_as_float(h0));
            unsigned u1 = f2tf32(p1 - __uint_as_float(h1));
            unsigned u2 = f2tf32(p2 - __uint_as_float(h2));
            unsigned u3 = f2tf32(p3 - __uint_as_float(h3));
            int col = wk * 16 + g * 8 + 2 * cL;
            *(float2*)&sf[S_PH + rA * 36 + col] =
                make_float2(__uint_as_float(h0), __uint_as_float(h1));
            *(float2*)&sf[S_PH + (rA + 8) * 36 + col] =
                make_float2(__uint_as_float(h2), __uint_as_float(h3));
            *(float2*)&sf[S_PL + rA * 36 + col] =
                make_float2(__uint_as_float(u0), __uint_as_float(u1));
            *(float2*)&sf[S_PL + (rA + 8) * 36 + col] =
                make_float2(__uint_as_float(u2), __uint_as_float(u3));
        }
        sum0 += __shfl_xor_sync(0xffffffffu, sum0, 1);
        sum0 += __shfl_xor_sync(0xffffffffu, sum0, 2);
        sum1 += __shfl_xor_sync(0xffffffffu, sum1, 1);
        sum1 += __shfl_xor_sync(0xffffffffu, sum1, 2);
        if (cL == 0) {
            sf[S_PS + wk * 64 + rA]     = sum0;
            sf[S_PS + wk * 64 + rA + 8] = sum1;
        }
        // scale o accumulators (PV rows == rA, rA+8)
        #pragma unroll
        for (int g = 0; g < 16; g++) {
            o[g][0] *= al0; o[g][1] *= al0;
            o[g][2] *= al1; o[g][3] *= al1;
        }
        __syncthreads();

        // m/l update (one warp per q-subtile)
        if (wk == 0 && cL == 0) {
            sf[S_M + rA]     = mn0;
            sf[S_M + rA + 8] = mn1;
            sf[S_L + rA]     = sf[S_L + rA]     * al0 + sf[S_PS + rA]     + sf[S_PS + 64 + rA];
            sf[S_L + rA + 8] = sf[S_L + rA + 8] * al1 + sf[S_PS + rA + 8] + sf[S_PS + 64 + rA + 8];
        }

        // ---- PV: o[16g][4] += p(64x32) @ v(32x128), 3-pass tf32 ----
        #pragma unroll
        for (int kb = 0; kb < 4; kb++) {
            const int pj = kb * 8 + cL;
            unsigned aph[4], apl[4];
            aph[0] = __float_as_uint(sf[S_PH + rA * 36 + pj]);
            aph[1] = __float_as_uint(sf[S_PH + (rA + 8) * 36 + pj]);
            aph[2] = __float_as_uint(sf[S_PH + rA * 36 + pj + 4]);
            aph[3] = __float_as_uint(sf[S_PH + (rA + 8) * 36 + pj + 4]);
            apl[0] = __float_as_uint(sf[S_PL + rA * 36 + pj]);
            apl[1] = __float_as_uint(sf[S_PL + (rA + 8) * 36 + pj]);
            apl[2] = __float_as_uint(sf[S_PL + rA * 36 + pj + 4]);
            apl[3] = __float_as_uint(sf[S_PL + (rA + 8) * 36 + pj + 4]);
            const int vb0 = (kb * 8 + cL) * 264;
            const int vb1 = (kb * 8 + cL + 4) * 264;
            #pragma unroll
            for (int g = 0; g < 16; g++) {
                const int vd = wk * 128 + g * 8 + rL;
                unsigned bh[2], bl[2];
                bh[0] = __float_as_uint(sf[S_VH + vb0 + vd]);
                bh[1] = __float_as_uint(sf[S_VH + vb1 + vd]);
                bl[0] = __float_as_uint(sf[S_VL + vb0 + vd]);
                bl[1] = __float_as_uint(sf[S_VL + vb1 + vd]);
                mma_tf32(o[g], aph, bh);
                mma_tf32(o[g], apl, bh);
                mma_tf32(o[g], aph, bl);
            }
        }
    }

    __syncthreads();
    // ---- epilogue: normalize, tf32-round (for O-proj), store ----
    const float il0 = 1.0f / sf[S_L + rA];
    const float il1 = 1.0f / sf[S_L + rA + 8];
    #pragma unroll
    for (int g = 0; g < 16; g++) {
        int col = h * HD + wk * 128 + g * 8 + 2 * cL;
        float* p0 = outp + (size_t)(t0 + rA) * HIDDEN + col;
        float* p1 = outp + (size_t)(t0 + rA + 8) * HIDDEN + col;
        *(float2*)p0 = make_float2(__uint_as_float(f2tf32(o[g][0] * il0)),
                                   __uint_as_float(f2tf32(o[g][1] * il0)));
        *(float2*)p1 = make_float2(__uint_as_float(f2tf32(o[g][2] * il1)),
                                   __uint_as_float(f2tf32(o[g][3] * il1)));
    }
}

// ---------------------------------------------------------------------------
// launch
// ---------------------------------------------------------------------------
extern "C" void kernel_launch(void* const* d_in, const int* in_sizes, int n_in,
                              void* d_out, int out_size)
{
    const float* hidden = (const float*)d_in[0];
    const float* w_qkv  = (const float*)d_in[1];
    const float* w_o    = (const float*)d_in[2];
    const float* cosp   = (const float*)d_in[3];
    const float* sinp   = (const float*)d_in[4];
    // d_in[5..8] (caches, slots, batch_size) unused: cache write+gather is identity.

    float* qkv;  cudaGetSymbolAddress((void**)&qkv,  g_qkv);
    float* attn; cudaGetSymbolAddress((void**)&attn, g_attn);
    float* hidR; cudaGetSymbolAddress((void**)&hidR, g_hid);
    float* wqR;  cudaGetSymbolAddress((void**)&wqR,  g_wq);
    float* woR;  cudaGetSymbolAddress((void**)&woR,  g_wo);

    cudaFuncSetAttribute(gemm_tc, cudaFuncAttributeMaxDynamicSharedMemorySize, GEMM_SMEM);
    cudaFuncSetAttribute(attn_tc, cudaFuncAttributeMaxDynamicSharedMemorySize, ATT_SMEM);

    // 0) tf32-round GEMM inputs once (rna; GEMM inner loop becomes cvt-free)
    round_tf32<<<(T_TOK * HIDDEN) / 1024, 256>>>(hidR, hidden);
    round_tf32<<<(QKV_W * HIDDEN) / 1024, 256>>>(wqR, w_qkv);
    round_tf32<<<(HIDDEN * HIDDEN) / 1024, 256>>>(woR, w_o);

    // 1) qkv = hidden @ w_qkv^T
    {
        dim3 grid(QKV_W / GTILE_N, T_TOK / GTILE_M);
        gemm_tc<<<grid, 256, GEMM_SMEM>>>(hidR, wqR, qkv, T_TOK, QKV_W, HIDDEN);
    }
    // 2) RoPE in place on q,k
    rope_kernel<<<(T_TOK * NHEAD * 32) / 256, 256>>>(qkv, cosp, sinp);
    // 3) tensor-core flash attention -> attn (tf32-rounded)
    {
        dim3 grid(SEQ / AQ, BATCH * NHEAD);
        attn_tc<<<grid, 256, ATT_SMEM>>>(qkv, attn);
    }
    // 4) out = attn @ w_o^T
    {
        dim3 grid(HIDDEN / GTILE_N, T_TOK / GTILE_M);
        gemm_tc<<<grid, 256, GEMM_SMEM>>>(attn, woR, (float*)d_out, T_TOK, HIDDEN, HIDDEN);
    }
}

// round 5
// speedup vs baseline: 2.4842x; 1.0844x over previous
#include <cuda_runtime.h>
#include <cuda_bf16.h>
#include <math.h>
#include <stdint.h>

// ---------------------------------------------------------------------------
// Problem constants
// ---------------------------------------------------------------------------
#define T_TOK   8192
#define HIDDEN  4096
#define NHEAD   16
#define HD      256
#define QKV_W   (3 * HIDDEN)     // 12288
#define BATCH   8
#define SEQ     1024
#define ROT_H   32               // rotary_dim/2

// Scratch (device globals: allocation-free rule)
__device__ float g_qkv[(size_t)T_TOK * QKV_W];     // 8192 x 12288
__device__ float g_attn[(size_t)T_TOK * HIDDEN];   // 8192 x 4096 (tf32-rounded)
__device__ float g_hid[(size_t)T_TOK * HIDDEN];    // rounded hidden
__device__ float g_wq [(size_t)QKV_W * HIDDEN];    // rounded w_qkv
__device__ float g_wo [(size_t)HIDDEN * HIDDEN];   // rounded w_o

// ---------------------------------------------------------------------------
// helpers
// ---------------------------------------------------------------------------
__device__ __forceinline__ uint32_t smem_u32(const void* p) {
    uint32_t a;
    asm("{ .reg .u64 t; cvta.to.shared.u64 t, %1; cvt.u32.u64 %0, t; }"
        : "=r"(a) : "l"(p));
    return a;
}

__device__ __forceinline__ unsigned f2tf32(float x) {
    unsigned u;
    asm("cvt.rna.tf32.f32 %0, %1;" : "=r"(u) : "f"(x));
    return u;
}

__device__ __forceinline__ void mma_tf32(float* d, const unsigned* a, const unsigned* b) {
    asm volatile(
        "mma.sync.aligned.m16n8k8.row.col.f32.tf32.tf32.f32 "
        "{%0,%1,%2,%3}, {%4,%5,%6,%7}, {%8,%9}, {%0,%1,%2,%3};\n"
        : "+f"(d[0]), "+f"(d[1]), "+f"(d[2]), "+f"(d[3])
        : "r"(a[0]), "r"(a[1]), "r"(a[2]), "r"(a[3]),
          "r"(b[0]), "r"(b[1]));
}

__device__ __forceinline__ void cp16(uint32_t dst, const void* src) {
    asm volatile("cp.async.cg.shared.global [%0], [%1], 16;"
                 :: "r"(dst), "l"(src) : "memory");
}
#define CP_COMMIT()  asm volatile("cp.async.commit_group;" ::: "memory")
#define CP_WAIT1()   asm volatile("cp.async.wait_group 1;" ::: "memory")
#define CP_WAIT0()   asm volatile("cp.async.wait_group 0;" ::: "memory")

// ---------------------------------------------------------------------------
// tf32 rounding pre-pass (rna) — makes GEMM inputs cvt-free
// ---------------------------------------------------------------------------
__global__ __launch_bounds__(256) void round_tf32(
    float* __restrict__ dst, const float* __restrict__ src)
{
    size_t i = (size_t)(blockIdx.x * 256 + threadIdx.x) * 4;
    float4 v = *(const float4*)(src + i);
    v.x = __uint_as_float(f2tf32(v.x));
    v.y = __uint_as_float(f2tf32(v.y));
    v.z = __uint_as_float(f2tf32(v.z));
    v.w = __uint_as_float(f2tf32(v.w));
    *(float4*)(dst + i) = v;
}

// ---------------------------------------------------------------------------
// tf32 mma.sync GEMM (NT), inputs pre-rounded: C[M][N] = sum_k A[M][K]*B[N][K]
// CTA 128x128, 128 threads (4 warps, 2x2 of 64x64 warp tiles), KTILE 32,
// 3-stage cp.async, ONE __syncthreads per k-tile, 2 CTAs/SM.
// ---------------------------------------------------------------------------
#define GTILE_M     128
#define GTILE_N     128
#define KTILE       32
#define A_STAGE_F   (GTILE_M * 32)          // 4096 floats (16 KB)
#define B_STAGE_F   (GTILE_N * 32)          // 4096 floats (16 KB)
#define STAGE_F     (A_STAGE_F + B_STAGE_F) // 8192 floats (32 KB)
#define NSTAGE      3
#define GEMM_SMEM   (NSTAGE * STAGE_F * 4)  // 98304 B

__global__ __launch_bounds__(128, 2) void gemm_tc(
    const float* __restrict__ A, const float* __restrict__ B,
    float* __restrict__ C, int M, int N, int K)
{
    extern __shared__ __align__(128) float smf[];
    const uint32_t sb = smem_u32(smf);

    const int tid  = threadIdx.x;
    const int lane = tid & 31;
    const int wid  = tid >> 5;
    const int wm   = wid >> 1;    // 0..1
    const int wn   = wid & 1;     // 0..1

    // CTA swizzle: groups of 8 m-tiles so weight panels stay L2-resident
    const int Nb = gridDim.x;
    const int Mb = gridDim.y;
    int linear = blockIdx.y * Nb + blockIdx.x;
    int group  = linear / (Nb * 8);
    int rem    = linear - group * (Nb * 8);
    int mstart = group * 8;
    int mspan  = Mb - mstart; if (mspan > 8) mspan = 8;
    int mb_id  = mstart + rem % mspan;
    int nb_id  = rem / mspan;
    const int m0 = mb_id * GTILE_M;
    const int n0 = nb_id * GTILE_N;

    // cp.async mapping: A stage 1024 chunks -> 8/thread; B same.
    const float* srcA[8];  uint32_t dstA[8];
    const float* srcB[8];  uint32_t dstB[8];
    #pragma unroll
    for (int i = 0; i < 8; i++) {
        int idx = tid + 128 * i;
        int row = idx >> 3, c4 = idx & 7;
        srcA[i] = A + (size_t)(m0 + row) * K + c4 * 4;
        dstA[i] = (uint32_t)((row * 8 + (c4 ^ (row & 7))) * 16);
        srcB[i] = B + (size_t)(n0 + row) * K + c4 * 4;
        dstB[i] = (uint32_t)(A_STAGE_F * 4 + (row * 8 + (c4 ^ (row & 7))) * 16);
    }

    const int NT = K >> 5;

    // prologue: fill 2 stages (tiles 0,1)
    #pragma unroll
    for (int s = 0; s < 2; s++) {
        const uint32_t st = sb + s * (STAGE_F * 4);
        #pragma unroll
        for (int i = 0; i < 8; i++) cp16(st + dstA[i], srcA[i] + s * KTILE);
        #pragma unroll
        for (int i = 0; i < 8; i++) cp16(st + dstB[i], srcB[i] + s * KTILE);
        CP_COMMIT();
    }

    float acc[4][8][4];
    #pragma unroll
    for (int f = 0; f < 4; f++)
        #pragma unroll
        for (int g = 0; g < 8; g++)
            #pragma unroll
            for (int r = 0; r < 4; r++) acc[f][g][r] = 0.f;

    const int r   = lane >> 2;
    const int c   = lane & 3;
    const int szx = r << 2;
    const int aRowBase = wm * 64 + r;
    const int bRowBase = wn * 64 + r;

    for (int kt = 0; kt < NT; kt++) {
        CP_WAIT1();          // tile kt's group complete
        __syncthreads();     // visibility + all warps done with stage (kt-1)%3

        // prefetch tile kt+2 into stage (kt+2)%3 == (kt-1)%3 (freed last iter)
        if (kt + 2 < NT) {
            const uint32_t st = sb + ((kt + 2) % 3) * (STAGE_F * 4);
            const int ko = (kt + 2) * KTILE;
            #pragma unroll
            for (int i = 0; i < 8; i++) cp16(st + dstA[i], srcA[i] + ko);
            #pragma unroll
            for (int i = 0; i < 8; i++) cp16(st + dstB[i], srcB[i] + ko);
        }
        CP_COMMIT();

        const float* sA = smf + (kt % 3) * STAGE_F;
        const float* sB = sA + A_STAGE_F;

        #pragma unroll
        for (int kb = 0; kb < 4; kb++) {
            const int col0 = (kb * 8 + c) ^ szx;
            const int col1 = col0 ^ 4;

            unsigned af[4][4];
            #pragma unroll
            for (int f = 0; f < 4; f++) {
                int base = (aRowBase + f * 16) * 32;
                af[f][0] = __float_as_uint(sA[base + col0]);
                af[f][1] = __float_as_uint(sA[base + 256 + col0]);
                af[f][2] = __float_as_uint(sA[base + col1]);
                af[f][3] = __float_as_uint(sA[base + 256 + col1]);
            }
            unsigned bf[8][2];
            #pragma unroll
            for (int g = 0; g < 8; g++) {
                int base = (bRowBase + g * 8) * 32;
                bf[g][0] = __float_as_uint(sB[base + col0]);
                bf[g][1] = __float_as_uint(sB[base + col1]);
            }
            #pragma unroll
            for (int f = 0; f < 4; f++)
                #pragma unroll
                for (int g = 0; g < 8; g++)
                    mma_tf32(acc[f][g], af[f], bf[g]);
        }
    }

    // epilogue
    #pragma unroll
    for (int f = 0; f < 4; f++) {
        int row = m0 + wm * 64 + f * 16 + r;
        #pragma unroll
        for (int g = 0; g < 8; g++) {
            int col = n0 + wn * 64 + g * 8 + c * 2;
            float* cp = C + (size_t)row * N + col;
            *(float2*)cp = make_float2(acc[f][g][0], acc[f][g][1]);
            *(float2*)(cp + (size_t)8 * N) = make_float2(acc[f][g][2], acc[f][g][3]);
        }
    }
}

// ---------------------------------------------------------------------------
// RoPE, in-place on q and k halves of qkv
// ---------------------------------------------------------------------------
__global__ __launch_bounds__(256) void rope_kernel(
    float* __restrict__ qkv, const float* __restrict__ cs, const float* __restrict__ sn)
{
    int idx = blockIdx.x * 256 + threadIdx.x;
    int d = idx & 31;
    int h = (idx >> 5) & 15;
    int t = idx >> 9;
    float c = cs[t * ROT_H + d];
    float s = sn[t * ROT_H + d];
    float* qp = qkv + (size_t)t * QKV_W + h * HD;
    float x1 = qp[d], x2 = qp[32 + d];
    qp[d]      = x1 * c - x2 * s;
    qp[32 + d] = x2 * c + x1 * s;
    float* kp = qp + HIDDEN;
    x1 = kp[d]; x2 = kp[32 + d];
    kp[d]      = x1 * c - x2 * s;
    kp[32 + d] = x2 * c + x1 * s;
}

// ---------------------------------------------------------------------------
// Tensor-core flash attention (3x-tf32 compensated, causal).
// CTA: 64 q-rows x one (b,h); k-tiles of 32. 8 warps: QK = 4q x 2k-halves,
// PV = 4q x 2d-halves. q pre-split hi/lo in smem; k raw (split on the fly);
// v split at load; p split at store, aliased onto dead k region.
// ---------------------------------------------------------------------------
#define AQ 64
#define AKT 32
// smem float offsets
#define S_QH 0                      // 64*256
#define S_QL 16384
#define S_KR 32768                  // 32*256 raw k (swizzled); aliases below
#define S_PH (S_KR + 0)             // 64*36
#define S_PL (S_KR + 2304)
#define S_PM (S_KR + 4608)          // 2*64 partial max
#define S_PS (S_KR + 4736)          // 2*64 partial sum
#define S_VH 40960                  // 32*264
#define S_VL 49408
#define S_M  57856                  // 64
#define S_L  57920                  // 64
#define ATT_SMEM   (57984 * 4)      // 231936 B

__global__ __launch_bounds__(256, 1) void attn_tc(
    const float* __restrict__ qkv, float* __restrict__ outp)
{
    extern __shared__ float sf[];
    const uint32_t sb = smem_u32(sf);
    const int tid = threadIdx.x, lane = tid & 31, w = tid >> 5;
    const int qt = 15 - blockIdx.x;                 // big tiles first
    const int bh = blockIdx.y;
    const int b = bh >> 4, h = bh & 15;
    const int t0 = b * SEQ + qt * AQ;
    const int wq = w & 3, wk = w >> 2;              // wk doubles as wd for PV
    const int cL = lane & 3;
    const int rL = lane >> 2;                       // 0..7
    const int rA = wq * 16 + rL;                    // owned q row (and +8)

    // ---- load q tile: scale (exact pow2), split hi/lo, swizzled store ----
    #pragma unroll
    for (int i = 0; i < 16; i++) {
        int idx = tid + 256 * i;
        int row = idx >> 6, c4 = idx & 63;
        float4 qv = *(const float4*)(qkv + (size_t)(t0 + row) * QKV_W + h * HD + c4 * 4);
        qv.x *= 0.0625f; qv.y *= 0.0625f; qv.z *= 0.0625f; qv.w *= 0.0625f;
        unsigned h0 = f2tf32(qv.x), h1 = f2tf32(qv.y), h2 = f2tf32(qv.z), h3 = f2tf32(qv.w);
        unsigned l0 = f2tf32(qv.x - __uint_as_float(h0));
        unsigned l1 = f2tf32(qv.y - __uint_as_float(h1));
        unsigned l2 = f2tf32(qv.z - __uint_as_float(h2));
        unsigned l3 = f2tf32(qv.w - __uint_as_float(h3));
        int off = row * 256 + ((c4 ^ (row & 7)) << 2);
        *(float4*)&sf[S_QH + off] = make_float4(__uint_as_float(h0), __uint_as_float(h1),
                                                __uint_as_float(h2), __uint_as_float(h3));
        *(float4*)&sf[S_QL + off] = make_float4(__uint_as_float(l0), __uint_as_float(l1),
                                                __uint_as_float(l2), __uint_as_float(l3));
    }
    if (tid < 64) { sf[S_M + tid] = -INFINITY; sf[S_L + tid] = 0.f; }

    float o[16][4];
    #pragma unroll
    for (int g = 0; g < 16; g++)
        #pragma unroll
        for (int r = 0; r < 4; r++) o[g][r] = 0.f;

    const int ktmax = 2 * qt + 1;

    for (int kt = 0; kt <= ktmax; kt++) {
        __syncthreads();    // p/v consumers done; q store done (iter 0)
        const int tk = b * SEQ + kt * AKT;
        // k: cp.async into swizzled raw tile
        #pragma unroll
        for (int i = 0; i < 8; i++) {
            int idx = tid + 256 * i;
            int row = idx >> 6, c4 = idx & 63;
            const float* src = qkv + (size_t)(tk + row) * QKV_W + HIDDEN + h * HD + c4 * 4;
            cp16(sb + (S_KR + row * 256 + ((c4 ^ (row & 7)) << 2)) * 4, src);
        }
        CP_COMMIT();
        // v: load raw, split hi/lo, padded store (stride 264)
        #pragma unroll
        for (int i = 0; i < 8; i++) {
            int idx = tid + 256 * i;
            int row = idx >> 6, c4 = idx & 63;
            float4 vv = *(const float4*)(qkv + (size_t)(tk + row) * QKV_W + 2 * HIDDEN + h * HD + c4 * 4);
            unsigned h0 = f2tf32(vv.x), h1 = f2tf32(vv.y), h2 = f2tf32(vv.z), h3 = f2tf32(vv.w);
            unsigned l0 = f2tf32(vv.x - __uint_as_float(h0));
            unsigned l1 = f2tf32(vv.y - __uint_as_float(h1));
            unsigned l2 = f2tf32(vv.z - __uint_as_float(h2));
            unsigned l3 = f2tf32(vv.w - __uint_as_float(h3));
            int off = row * 264 + c4 * 4;
            *(float4*)&sf[S_VH + off] = make_float4(__uint_as_float(h0), __uint_as_float(h1),
                                                    __uint_as_float(h2), __uint_as_float(h3));
            *(float4*)&sf[S_VL + off] = make_float4(__uint_as_float(l0), __uint_as_float(l1),
                                                    __uint_as_float(l2), __uint_as_float(l3));
        }
        CP_WAIT0();
        __syncthreads();

        // ---- QK: 3-pass tf32 over 32 k8-blocks ----
        float sacc[2][4];
        #pragma unroll
        for (int g = 0; g < 2; g++)
            #pragma unroll
            for (int r = 0; r < 4; r++) sacc[g][r] = 0.f;

        #pragma unroll
        for (int kb = 0; kb < 32; kb++) {
            const int c4x = (2 * kb) ^ rL;
            const int a0 = rA * 256 + (c4x << 2) + cL;
            const int a2 = rA * 256 + ((c4x ^ 1) << 2) + cL;
            unsigned ah[4], al[4];
            ah[0] = __float_as_uint(sf[S_QH + a0]);
            ah[1] = __float_as_uint(sf[S_QH + a0 + 2048]);
            ah[2] = __float_as_uint(sf[S_QH + a2]);
            ah[3] = __float_as_uint(sf[S_QH + a2 + 2048]);
            al[0] = __float_as_uint(sf[S_QL + a0]);
            al[1] = __float_as_uint(sf[S_QL + a0 + 2048]);
            al[2] = __float_as_uint(sf[S_QL + a2]);
            al[3] = __float_as_uint(sf[S_QL + a2 + 2048]);
            #pragma unroll
            for (int g = 0; g < 2; g++) {
                int kbase = S_KR + (wk * 16 + g * 8 + rL) * 256;
                float r0 = sf[kbase + (c4x << 2) + cL];
                float r1 = sf[kbase + ((c4x ^ 1) << 2) + cL];
                unsigned bh[2], bl[2];
                bh[0] = f2tf32(r0); bl[0] = f2tf32(r0 - __uint_as_float(bh[0]));
                bh[1] = f2tf32(r1); bl[1] = f2tf32(r1 - __uint_as_float(bh[1]));
                mma_tf32(sacc[g], ah, bh);
                mma_tf32(sacc[g], al, bh);
                mma_tf32(sacc[g], ah, bl);
            }
        }

        // causal mask (only tiles touching the diagonal)
        if (kt >= 2 * qt) {
            #pragma unroll
            for (int g = 0; g < 2; g++)
                #pragma unroll
                for (int r = 0; r < 4; r++) {
                    int col = kt * AKT + wk * 16 + g * 8 + 2 * cL + (r & 1);
                    int row = qt * AQ + rA + 8 * (r >> 1);
                    if (col > row) sacc[g][r] = -1e30f;
                }
        }
        __syncthreads();    // all QK smem reads done; kr region reusable

        // ---- partial row max over this warp's 16 cols ----
        float mx0 = fmaxf(fmaxf(sacc[0][0], sacc[0][1]), fmaxf(sacc[1][0], sacc[1][1]));
        float mx1 = fmaxf(fmaxf(sacc[0][2], sacc[0][3]), fmaxf(sacc[1][2], sacc[1][3]));
        mx0 = fmaxf(mx0, __shfl_xor_sync(0xffffffffu, mx0, 1));
        mx0 = fmaxf(mx0, __shfl_xor_sync(0xffffffffu, mx0, 2));
        mx1 = fmaxf(mx1, __shfl_xor_sync(0xffffffffu, mx1, 1));
        mx1 = fmaxf(mx1, __shfl_xor_sync(0xffffffffu, mx1, 2));
        if (cL == 0) {
            sf[S_PM + wk * 64 + rA]     = mx0;
            sf[S_PM + wk * 64 + rA + 8] = mx1;
        }
        __syncthreads();

        // ---- stats + p = exp(s - m_new), split, store; o-scale ----
        float mo0 = sf[S_M + rA], mo1 = sf[S_M + rA + 8];
        float mn0 = fmaxf(mo0, fmaxf(sf[S_PM + rA],     sf[S_PM + 64 + rA]));
        float mn1 = fmaxf(mo1, fmaxf(sf[S_PM + rA + 8], sf[S_PM + 64 + rA + 8]));
        float al0 = __expf(mo0 - mn0), al1 = __expf(mo1 - mn1);

        float sum0 = 0.f, sum1 = 0.f;
        #pragma unroll
        for (int g = 0; g < 2; g++) {
            float p0 = __expf(sacc[g][0] - mn0);
            float p1 = __expf(sacc[g][1] - mn0);
            float p2 = __expf(sacc[g][2] - mn1);
            float p3 = __expf(sacc[g][3] - mn1);
            sum0 += p0 + p1; sum1 += p2 + p3;
            unsigned h0 = f2tf32(p0), h1 = f2tf32(p1), h2 = f2tf32(p2), h3 = f2tf32(p3);
            unsigned u0 = f2tf32(p0 - __uint_as_float(h0));
            unsigned u1 = f2tf32(p1 - __uint_as_float(h1));
            unsigned u2 = f2tf32(p2 - __uint_as_float(h2));
            unsigned u3 = f2tf32(p3 - __uint_as_float(h3));
            int col = wk * 16 + g * 8 + 2 * cL;
            *(float2*)&sf[S_PH + rA * 36 + col] =
                make_float2(__uint_as_float(h0), __uint_as_float(h1));
            *(float2*)&sf[S_PH + (rA + 8) * 36 + col] =
                make_float2(__uint_as_float(h2), __uint_as_float(h3));
            *(float2*)&sf[S_PL + rA * 36 + col] =
                make_float2(__uint_as_float(u0), __uint_as_float(u1));
            *(float2*)&sf[S_PL + (rA + 8) * 36 + col] =
                make_float2(__uint_as_float(u2), __uint_as_float(u3));
        }
        sum0 += __shfl_xor_sync(0xffffffffu, sum0, 1);
        sum0 += __shfl_xor_sync(0xffffffffu, sum0, 2);
        sum1 += __shfl_xor_sync(0xffffffffu, sum1, 1);
        sum1 += __shfl_xor_sync(0xffffffffu, sum1, 2);
        if (cL == 0) {
            sf[S_PS + wk * 64 + rA]     = sum0;
            sf[S_PS + wk * 64 + rA + 8] = sum1;
        }
        // scale o accumulators (PV rows == rA, rA+8)
        #pragma unroll
        for (int g = 0; g < 16; g++) {
            o[g][0] *= al0; o[g][1] *= al0;
            o[g][2] *= al1; o[g][3] *= al1;
        }
        __syncthreads();

        // m/l update (one warp per q-subtile)
        if (wk == 0 && cL == 0) {
            sf[S_M + rA]     = mn0;
            sf[S_M + rA + 8] = mn1;
            sf[S_L + rA]     = sf[S_L + rA]     * al0 + sf[S_PS + rA]     + sf[S_PS + 64 + rA];
            sf[S_L + rA + 8] = sf[S_L + rA + 8] * al1 + sf[S_PS + rA + 8] + sf[S_PS + 64 + rA + 8];
        }

        // ---- PV: o += p(64x32) @ v(32x128), 3-pass tf32 ----
        #pragma unroll
        for (int kb = 0; kb < 4; kb++) {
            const int pj = kb * 8 + cL;
            unsigned aph[4], apl[4];
            aph[0] = __float_as_uint(sf[S_PH + rA * 36 + pj]);
            aph[1] = __float_as_uint(sf[S_PH + (rA + 8) * 36 + pj]);
            aph[2] = __float_as_uint(sf[S_PH + rA * 36 + pj + 4]);
            aph[3] = __float_as_uint(sf[S_PH + (rA + 8) * 36 + pj + 4]);
            apl[0] = __float_as_uint(sf[S_PL + rA * 36 + pj]);
            apl[1] = __float_as_uint(sf[S_PL + (rA + 8) * 36 + pj]);
            apl[2] = __float_as_uint(sf[S_PL + rA * 36 + pj + 4]);
            apl[3] = __float_as_uint(sf[S_PL + (rA + 8) * 36 + pj + 4]);
            const int vb0 = (kb * 8 + cL) * 264;
            const int vb1 = (kb * 8 + cL + 4) * 264;
            #pragma unroll
            for (int g = 0; g < 16; g++) {
                const int vd = wk * 128 + g * 8 + rL;
                unsigned bh[2], bl[2];
                bh[0] = __float_as_uint(sf[S_VH + vb0 + vd]);
                bh[1] = __float_as_uint(sf[S_VH + vb1 + vd]);
                bl[0] = __float_as_uint(sf[S_VL + vb0 + vd]);
                bl[1] = __float_as_uint(sf[S_VL + vb1 + vd]);
                mma_tf32(o[g], aph, bh);
                mma_tf32(o[g], apl, bh);
                mma_tf32(o[g], aph, bl);
            }
        }
    }

    __syncthreads();
    // ---- epilogue: normalize, tf32-round (for O-proj), store ----
    const float il0 = 1.0f / sf[S_L + rA];
    const float il1 = 1.0f / sf[S_L + rA + 8];
    #pragma unroll
    for (int g = 0; g < 16; g++) {
        int col = h * HD + wk * 128 + g * 8 + 2 * cL;
        float* p0 = outp + (size_t)(t0 + rA) * HIDDEN + col;
        float* p1 = outp + (size_t)(t0 + rA + 8) * HIDDEN + col;
        *(float2*)p0 = make_float2(__uint_as_float(f2tf32(o[g][0] * il0)),
                                   __uint_as_float(f2tf32(o[g][1] * il0)));
        *(float2*)p1 = make_float2(__uint_as_float(f2tf32(o[g][2] * il1)),
                                   __uint_as_float(f2tf32(o[g][3] * il1)));
    }
}

// ---------------------------------------------------------------------------
// launch
// ---------------------------------------------------------------------------
extern "C" void kernel_launch(void* const* d_in, const int* in_sizes, int n_in,
                              void* d_out, int out_size)
{
    const float* hidden = (const float*)d_in[0];
    const float* w_qkv  = (const float*)d_in[1];
    const float* w_o    = (const float*)d_in[2];
    const float* cosp   = (const float*)d_in[3];
    const float* sinp   = (const float*)d_in[4];
    // d_in[5..8] (caches, slots, batch_size) unused: cache write+gather is identity.

    float* qkv;  cudaGetSymbolAddress((void**)&qkv,  g_qkv);
    float* attn; cudaGetSymbolAddress((void**)&attn, g_attn);
    float* hidR; cudaGetSymbolAddress((void**)&hidR, g_hid);
    float* wqR;  cudaGetSymbolAddress((void**)&wqR,  g_wq);
    float* woR;  cudaGetSymbolAddress((void**)&woR,  g_wo);

    cudaFuncSetAttribute(gemm_tc, cudaFuncAttributeMaxDynamicSharedMemorySize, GEMM_SMEM);
    cudaFuncSetAttribute(attn_tc, cudaFuncAttributeMaxDynamicSharedMemorySize, ATT_SMEM);

    // 0) tf32-round GEMM inputs once (rna; GEMM inner loop is cvt-free)
    round_tf32<<<(T_TOK * HIDDEN) / 1024, 256>>>(hidR, hidden);
    round_tf32<<<(QKV_W * HIDDEN) / 1024, 256>>>(wqR, w_qkv);
    round_tf32<<<(HIDDEN * HIDDEN) / 1024, 256>>>(woR, w_o);

    // 1) qkv = hidden @ w_qkv^T
    {
        dim3 grid(QKV_W / GTILE_N, T_TOK / GTILE_M);   // (96, 64)
        gemm_tc<<<grid, 128, GEMM_SMEM>>>(hidR, wqR, qkv, T_TOK, QKV_W, HIDDEN);
    }
    // 2) RoPE in place on q,k
    rope_kernel<<<(T_TOK * NHEAD * 32) / 256, 256>>>(qkv, cosp, sinp);
    // 3) tensor-core flash attention -> attn (tf32-rounded)
    {
        dim3 grid(SEQ / AQ, BATCH * NHEAD);
        attn_tc<<<grid, 256, ATT_SMEM>>>(qkv, attn);
    }
    // 4) out = attn @ w_o^T
    {
        dim3 grid(HIDDEN / GTILE_N, T_TOK / GTILE_M);  // (32, 64)
        gemm_tc<<<grid, 128, GEMM_SMEM>>>(attn, woR, (float*)d_out, T_TOK, HIDDEN, HIDDEN);
    }
}

// round 6
// speedup vs baseline: 3.5334x; 1.4224x over previous
#include <cuda_runtime.h>
#include <cuda_fp16.h>
#include <math.h>
#include <stdint.h>

// ---------------------------------------------------------------------------
// Problem constants
// ---------------------------------------------------------------------------
#define T_TOK   8192
#define HIDDEN  4096
#define NHEAD   16
#define HD      256
#define QKV_W   (3 * HIDDEN)     // 12288
#define BATCH   8
#define SEQ     1024
#define ROT_H   32               // rotary_dim/2

// Scratch (device globals: allocation-free rule)
__device__ float  g_qkv[(size_t)T_TOK * QKV_W];      // 8192 x 12288 fp32
__device__ __half g_attn16[(size_t)T_TOK * HIDDEN];  // attention out (fp16)
__device__ __half g_hid16[(size_t)T_TOK * HIDDEN];   // fp16 hidden
__device__ __half g_wq16 [(size_t)QKV_W * HIDDEN];   // fp16 w_qkv
__device__ __half g_wo16 [(size_t)HIDDEN * HIDDEN];  // fp16 w_o

// ---------------------------------------------------------------------------
// helpers
// ---------------------------------------------------------------------------
__device__ __forceinline__ uint32_t smem_u32(const void* p) {
    uint32_t a;
    asm("{ .reg .u64 t; cvta.to.shared.u64 t, %1; cvt.u32.u64 %0, t; }"
        : "=r"(a) : "l"(p));
    return a;
}

__device__ __forceinline__ unsigned f2tf32(float x) {
    unsigned u;
    asm("cvt.rna.tf32.f32 %0, %1;" : "=r"(u) : "f"(x));
    return u;
}

__device__ __forceinline__ void mma_tf32(float* d, const unsigned* a, const unsigned* b) {
    asm volatile(
        "mma.sync.aligned.m16n8k8.row.col.f32.tf32.tf32.f32 "
        "{%0,%1,%2,%3}, {%4,%5,%6,%7}, {%8,%9}, {%0,%1,%2,%3};\n"
        : "+f"(d[0]), "+f"(d[1]), "+f"(d[2]), "+f"(d[3])
        : "r"(a[0]), "r"(a[1]), "r"(a[2]), "r"(a[3]),
          "r"(b[0]), "r"(b[1]));
}

__device__ __forceinline__ void mma_f16(float* d, const unsigned* a, const unsigned* b) {
    asm volatile(
        "mma.sync.aligned.m16n8k16.row.col.f32.f16.f16.f32 "
        "{%0,%1,%2,%3}, {%4,%5,%6,%7}, {%8,%9}, {%0,%1,%2,%3};\n"
        : "+f"(d[0]), "+f"(d[1]), "+f"(d[2]), "+f"(d[3])
        : "r"(a[0]), "r"(a[1]), "r"(a[2]), "r"(a[3]),
          "r"(b[0]), "r"(b[1]));
}

__device__ __forceinline__ void ldsm_x4(unsigned* r, uint32_t addr) {
    asm volatile("ldmatrix.sync.aligned.m8n8.x4.shared.b16 {%0,%1,%2,%3}, [%4];"
        : "=r"(r[0]), "=r"(r[1]), "=r"(r[2]), "=r"(r[3]) : "r"(addr));
}

__device__ __forceinline__ void cp16(uint32_t dst, const void* src) {
    asm volatile("cp.async.cg.shared.global [%0], [%1], 16;"
                 :: "r"(dst), "l"(src) : "memory");
}
#define CP_COMMIT()  asm volatile("cp.async.commit_group;" ::: "memory")
#define CP_WAIT1()   asm volatile("cp.async.wait_group 1;" ::: "memory")
#define CP_WAIT0()   asm volatile("cp.async.wait_group 0;" ::: "memory")

// ---------------------------------------------------------------------------
// fp32 -> fp16 conversion pre-pass (rn)
// ---------------------------------------------------------------------------
__global__ __launch_bounds__(256) void f2h_kernel(
    __half* __restrict__ dst, const float* __restrict__ src)
{
    size_t i = (size_t)(blockIdx.x * 256 + threadIdx.x) * 4;
    float4 v = *(const float4*)(src + i);
    __half2 h0 = __floats2half2_rn(v.x, v.y);
    __half2 h1 = __floats2half2_rn(v.z, v.w);
    *(__half2*)(dst + i)     = h0;
    *(__half2*)(dst + i + 2) = h1;
}

// ---------------------------------------------------------------------------
// fp16 mma.sync GEMM (NT): C[M][N] = sum_k A[M][K]*B[N][K], fp32 accumulate.
// CTA 128x128, 128 threads (2x2 warps of 64x64), KTILE 32, 3-stage cp.async,
// one __syncthreads per k-tile, 2 CTAs/SM. smem rows padded to 80B ->
// ldmatrix conflict-free (5r mod 8 cycles all chunks).
// ---------------------------------------------------------------------------
#define GTILE_M   128
#define GTILE_N   128
#define KTILE     32
#define ROW_B     80                       // 64B data + 16B pad
#define A_ST_B    (128 * ROW_B)            // 10240 B
#define STAGE_B   (2 * A_ST_B)             // 20480 B
#define GEMM_SMEM (3 * STAGE_B)            // 61440 B

__global__ __launch_bounds__(128, 2) void gemm_h(
    const __half* __restrict__ A, const __half* __restrict__ B,
    float* __restrict__ C, int M, int N, int K)
{
    extern __shared__ __align__(128) char smc[];
    const uint32_t sb = smem_u32(smc);

    const int tid  = threadIdx.x;
    const int lane = tid & 31;
    const int wid  = tid >> 5;
    const int wm   = wid >> 1;    // 0..1
    const int wn   = wid & 1;     // 0..1

    // CTA swizzle: groups of 8 m-tiles keep weight panels L2-resident
    const int Nb = gridDim.x;
    const int Mb = gridDim.y;
    int linear = blockIdx.y * Nb + blockIdx.x;
    int group  = linear / (Nb * 8);
    int rem    = linear - group * (Nb * 8);
    int mstart = group * 8;
    int mspan  = Mb - mstart; if (mspan > 8) mspan = 8;
    int mb_id  = mstart + rem % mspan;
    int nb_id  = rem / mspan;
    const int m0 = mb_id * GTILE_M;
    const int n0 = nb_id * GTILE_N;

    // cp.async mapping: 512 16B-chunks per tile side, 4 per thread each.
    const __half* srcA[4];  uint32_t dstA[4];
    const __half* srcB[4];  uint32_t dstB[4];
    #pragma unroll
    for (int i = 0; i < 4; i++) {
        int idx = tid + 128 * i;
        int row = idx >> 2, c = idx & 3;
        srcA[i] = A + (size_t)(m0 + row) * K + c * 8;
        dstA[i] = (uint32_t)(row * ROW_B + c * 16);
        srcB[i] = B + (size_t)(n0 + row) * K + c * 8;
        dstB[i] = (uint32_t)(A_ST_B + row * ROW_B + c * 16);
    }

    const int NT = K >> 5;

    // prologue: fill stages 0,1
    #pragma unroll
    for (int s = 0; s < 2; s++) {
        const uint32_t st = sb + s * STAGE_B;
        #pragma unroll
        for (int i = 0; i < 4; i++) cp16(st + dstA[i], srcA[i] + s * KTILE);
        #pragma unroll
        for (int i = 0; i < 4; i++) cp16(st + dstB[i], srcB[i] + s * KTILE);
        CP_COMMIT();
    }

    float acc[4][8][4];
    #pragma unroll
    for (int f = 0; f < 4; f++)
        #pragma unroll
        for (int g = 0; g < 8; g++)
            #pragma unroll
            for (int r = 0; r < 4; r++) acc[f][g][r] = 0.f;

    // ldmatrix lane addressing (within stage):
    // A x4: lanes 0-7 rows 0-7 @k0 | 8-15 rows 8-15 @k0 | 16-23 rows 0-7 @k8 | 24-31 rows 8-15 @k8
    const uint32_t aLane = (uint32_t)((wm * 64 + (lane & 15)) * ROW_B + ((lane >> 4) << 4));
    // B x4 (two n8 tiles): lanes 0-7 n0-7@k0 | 8-15 n0-7@k8 | 16-23 n8-15@k0 | 24-31 n8-15@k8
    const uint32_t bLane = (uint32_t)(A_ST_B +
        (wn * 64 + ((lane >> 4) << 3) + (lane & 7)) * ROW_B + (((lane >> 3) & 1) << 4));

    for (int kt = 0; kt < NT; kt++) {
        CP_WAIT1();
        __syncthreads();

        if (kt + 2 < NT) {
            const uint32_t st = sb + ((kt + 2) % 3) * STAGE_B;
            const int ko = (kt + 2) * KTILE;
            #pragma unroll
            for (int i = 0; i < 4; i++) cp16(st + dstA[i], srcA[i] + ko);
            #pragma unroll
            for (int i = 0; i < 4; i++) cp16(st + dstB[i], srcB[i] + ko);
        }
        CP_COMMIT();

        const uint32_t stb = sb + (kt % 3) * STAGE_B;
        #pragma unroll
        for (int s = 0; s < 2; s++) {
            unsigned af[4][4], bf[4][4];
            #pragma unroll
            for (int f = 0; f < 4; f++)
                ldsm_x4(af[f], stb + aLane + f * (16 * ROW_B) + s * 32);
            #pragma unroll
            for (int g2 = 0; g2 < 4; g2++)
                ldsm_x4(bf[g2], stb + bLane + g2 * (16 * ROW_B) + s * 32);
            #pragma unroll
            for (int f = 0; f < 4; f++)
                #pragma unroll
                for (int g = 0; g < 8; g++)
                    mma_f16(acc[f][g], af[f], &bf[g >> 1][(g & 1) * 2]);
        }
    }

    // epilogue
    const int r = lane >> 2;
    const int c = lane & 3;
    #pragma unroll
    for (int f = 0; f < 4; f++) {
        int row = m0 + wm * 64 + f * 16 + r;
        #pragma unroll
        for (int g = 0; g < 8; g++) {
            int col = n0 + wn * 64 + g * 8 + c * 2;
            float* cp = C + (size_t)row * N + col;
            *(float2*)cp = make_float2(acc[f][g][0], acc[f][g][1]);
            *(float2*)(cp + (size_t)8 * N) = make_float2(acc[f][g][2], acc[f][g][3]);
        }
    }
}

// ---------------------------------------------------------------------------
// RoPE, in-place on q and k halves of qkv
// ---------------------------------------------------------------------------
__global__ __launch_bounds__(256) void rope_kernel(
    float* __restrict__ qkv, const float* __restrict__ cs, const float* __restrict__ sn)
{
    int idx = blockIdx.x * 256 + threadIdx.x;
    int d = idx & 31;
    int h = (idx >> 5) & 15;
    int t = idx >> 9;
    float c = cs[t * ROT_H + d];
    float s = sn[t * ROT_H + d];
    float* qp = qkv + (size_t)t * QKV_W + h * HD;
    float x1 = qp[d], x2 = qp[32 + d];
    qp[d]      = x1 * c - x2 * s;
    qp[32 + d] = x2 * c + x1 * s;
    float* kp = qp + HIDDEN;
    x1 = kp[d]; x2 = kp[32 + d];
    kp[d]      = x1 * c - x2 * s;
    kp[32 + d] = x2 * c + x1 * s;
}

// ---------------------------------------------------------------------------
// Tensor-core flash attention (3x-tf32 compensated, causal). Unchanged from R5
// except the epilogue stores fp16 (input to the fp16 O-proj GEMM).
// ---------------------------------------------------------------------------
#define AQ 64
#define AKT 32
#define S_QH 0
#define S_QL 16384
#define S_KR 32768
#define S_PH (S_KR + 0)
#define S_PL (S_KR + 2304)
#define S_PM (S_KR + 4608)
#define S_PS (S_KR + 4736)
#define S_VH 40960
#define S_VL 49408
#define S_M  57856
#define S_L  57920
#define ATT_SMEM   (57984 * 4)

__global__ __launch_bounds__(256, 1) void attn_tc(
    const float* __restrict__ qkv, __half* __restrict__ outp)
{
    extern __shared__ float sf[];
    const uint32_t sb = smem_u32(sf);
    const int tid = threadIdx.x, lane = tid & 31, w = tid >> 5;
    const int qt = 15 - blockIdx.x;
    const int bh = blockIdx.y;
    const int b = bh >> 4, h = bh & 15;
    const int t0 = b * SEQ + qt * AQ;
    const int wq = w & 3, wk = w >> 2;
    const int cL = lane & 3;
    const int rL = lane >> 2;
    const int rA = wq * 16 + rL;

    #pragma unroll
    for (int i = 0; i < 16; i++) {
        int idx = tid + 256 * i;
        int row = idx >> 6, c4 = idx & 63;
        float4 qv = *(const float4*)(qkv + (size_t)(t0 + row) * QKV_W + h * HD + c4 * 4);
        qv.x *= 0.0625f; qv.y *= 0.0625f; qv.z *= 0.0625f; qv.w *= 0.0625f;
        unsigned h0 = f2tf32(qv.x), h1 = f2tf32(qv.y), h2 = f2tf32(qv.z), h3 = f2tf32(qv.w);
        unsigned l0 = f2tf32(qv.x - __uint_as_float(h0));
        unsigned l1 = f2tf32(qv.y - __uint_as_float(h1));
        unsigned l2 = f2tf32(qv.z - __uint_as_float(h2));
        unsigned l3 = f2tf32(qv.w - __uint_as_float(h3));
        int off = row * 256 + ((c4 ^ (row & 7)) << 2);
        *(float4*)&sf[S_QH + off] = make_float4(__uint_as_float(h0), __uint_as_float(h1),
                                                __uint_as_float(h2), __uint_as_float(h3));
        *(float4*)&sf[S_QL + off] = make_float4(__uint_as_float(l0), __uint_as_float(l1),
                                                __uint_as_float(l2), __uint_as_float(l3));
    }
    if (tid < 64) { sf[S_M + tid] = -INFINITY; sf[S_L + tid] = 0.f; }

    float o[16][4];
    #pragma unroll
    for (int g = 0; g < 16; g++)
        #pragma unroll
        for (int r = 0; r < 4; r++) o[g][r] = 0.f;

    const int ktmax = 2 * qt + 1;

    for (int kt = 0; kt <= ktmax; kt++) {
        __syncthreads();
        const int tk = b * SEQ + kt * AKT;
        #pragma unroll
        for (int i = 0; i < 8; i++) {
            int idx = tid + 256 * i;
            int row = idx >> 6, c4 = idx & 63;
            const float* src = qkv + (size_t)(tk + row) * QKV_W + HIDDEN + h * HD + c4 * 4;
            cp16(sb + (S_KR + row * 256 + ((c4 ^ (row & 7)) << 2)) * 4, src);
        }
        CP_COMMIT();
        #pragma unroll
        for (int i = 0; i < 8; i++) {
            int idx = tid + 256 * i;
            int row = idx >> 6, c4 = idx & 63;
            float4 vv = *(const float4*)(qkv + (size_t)(tk + row) * QKV_W + 2 * HIDDEN + h * HD + c4 * 4);
            unsigned h0 = f2tf32(vv.x), h1 = f2tf32(vv.y), h2 = f2tf32(vv.z), h3 = f2tf32(vv.w);
            unsigned l0 = f2tf32(vv.x - __uint_as_float(h0));
            unsigned l1 = f2tf32(vv.y - __uint_as_float(h1));
            unsigned l2 = f2tf32(vv.z - __uint_as_float(h2));
            unsigned l3 = f2tf32(vv.w - __uint_as_float(h3));
            int off = row * 264 + c4 * 4;
            *(float4*)&sf[S_VH + off] = make_float4(__uint_as_float(h0), __uint_as_float(h1),
                                                    __uint_as_float(h2), __uint_as_float(h3));
            *(float4*)&sf[S_VL + off] = make_float4(__uint_as_float(l0), __uint_as_float(l1),
                                                    __uint_as_float(l2), __uint_as_float(l3));
        }
        CP_WAIT0();
        __syncthreads();

        float sacc[2][4];
        #pragma unroll
        for (int g = 0; g < 2; g++)
            #pragma unroll
            for (int r = 0; r < 4; r++) sacc[g][r] = 0.f;

        #pragma unroll
        for (int kb = 0; kb < 32; kb++) {
            const int c4x = (2 * kb) ^ rL;
            const int a0 = rA * 256 + (c4x << 2) + cL;
            const int a2 = rA * 256 + ((c4x ^ 1) << 2) + cL;
            unsigned ah[4], al[4];
            ah[0] = __float_as_uint(sf[S_QH + a0]);
            ah[1] = __float_as_uint(sf[S_QH + a0 + 2048]);
            ah[2] = __float_as_uint(sf[S_QH + a2]);
            ah[3] = __float_as_uint(sf[S_QH + a2 + 2048]);
            al[0] = __float_as_uint(sf[S_QL + a0]);
            al[1] = __float_as_uint(sf[S_QL + a0 + 2048]);
            al[2] = __float_as_uint(sf[S_QL + a2]);
            al[3] = __float_as_uint(sf[S_QL + a2 + 2048]);
            #pragma unroll
            for (int g = 0; g < 2; g++) {
                int kbase = S_KR + (wk * 16 + g * 8 + rL) * 256;
                float r0 = sf[kbase + (c4x << 2) + cL];
                float r1 = sf[kbase + ((c4x ^ 1) << 2) + cL];
                unsigned bh[2], bl[2];
                bh[0] = f2tf32(r0); bl[0] = f2tf32(r0 - __uint_as_float(bh[0]));
                bh[1] = f2tf32(r1); bl[1] = f2tf32(r1 - __uint_as_float(bh[1]));
                mma_tf32(sacc[g], ah, bh);
                mma_tf32(sacc[g], al, bh);
                mma_tf32(sacc[g], ah, bl);
            }
        }

        if (kt >= 2 * qt) {
            #pragma unroll
            for (int g = 0; g < 2; g++)
                #pragma unroll
                for (int r = 0; r < 4; r++) {
                    int col = kt * AKT + wk * 16 + g * 8 + 2 * cL + (r & 1);
                    int row = qt * AQ + rA + 8 * (r >> 1);
                    if (col > row) sacc[g][r] = -1e30f;
                }
        }
        __syncthreads();

        float mx0 = fmaxf(fmaxf(sacc[0][0], sacc[0][1]), fmaxf(sacc[1][0], sacc[1][1]));
        float mx1 = fmaxf(fmaxf(sacc[0][2], sacc[0][3]), fmaxf(sacc[1][2], sacc[1][3]));
        mx0 = fmaxf(mx0, __shfl_xor_sync(0xffffffffu, mx0, 1));
        mx0 = fmaxf(mx0, __shfl_xor_sync(0xffffffffu, mx0, 2));
        mx1 = fmaxf(mx1, __shfl_xor_sync(0xffffffffu, mx1, 1));
        mx1 = fmaxf(mx1, __shfl_xor_sync(0xffffffffu, mx1, 2));
        if (cL == 0) {
            sf[S_PM + wk * 64 + rA]     = mx0;
            sf[S_PM + wk * 64 + rA + 8] = mx1;
        }
        __syncthreads();

        float mo0 = sf[S_M + rA], mo1 = sf[S_M + rA + 8];
        float mn0 = fmaxf(mo0, fmaxf(sf[S_PM + rA],     sf[S_PM + 64 + rA]));
        float mn1 = fmaxf(mo1, fmaxf(sf[S_PM + rA + 8], sf[S_PM + 64 + rA + 8]));
        float al0 = __expf(mo0 - mn0), al1 = __expf(mo1 - mn1);

        float sum0 = 0.f, sum1 = 0.f;
        #pragma unroll
        for (int g = 0; g < 2; g++) {
            float p0 = __expf(sacc[g][0] - mn0);
            float p1 = __expf(sacc[g][1] - mn0);
            float p2 = __expf(sacc[g][2] - mn1);
            float p3 = __expf(sacc[g][3] - mn1);
            sum0 += p0 + p1; sum1 += p2 + p3;
            unsigned h0 = f2tf32(p0), h1 = f2tf32(p1), h2 = f2tf32(p2), h3 = f2tf32(p3);
            unsigned u0 = f2tf32(p0 - __uint_as_float(h0));
            unsigned u1 = f2tf32(p1 - __uint_as_float(h1));
            unsigned u2 = f2tf32(p2 - __uint_as_float(h2));
            unsigned u3 = f2tf32(p3 - __uint_as_float(h3));
            int col = wk * 16 + g * 8 + 2 * cL;
            *(float2*)&sf[S_PH + rA * 36 + col] =
                make_float2(__uint_as_float(h0), __uint_as_float(h1));
            *(float2*)&sf[S_PH + (rA + 8) * 36 + col] =
                make_float2(__uint_as_float(h2), __uint_as_float(h3));
            *(float2*)&sf[S_PL + rA * 36 + col] =
                make_float2(__uint_as_float(u0), __uint_as_float(u1));
            *(float2*)&sf[S_PL + (rA + 8) * 36 + col] =
                make_float2(__uint_as_float(u2), __uint_as_float(u3));
        }
        sum0 += __shfl_xor_sync(0xffffffffu, sum0, 1);
        sum0 += __shfl_xor_sync(0xffffffffu, sum0, 2);
        sum1 += __shfl_xor_sync(0xffffffffu, sum1, 1);
        sum1 += __shfl_xor_sync(0xffffffffu, sum1, 2);
        if (cL == 0) {
            sf[S_PS + wk * 64 + rA]     = sum0;
            sf[S_PS + wk * 64 + rA + 8] = sum1;
        }
        #pragma unroll
        for (int g = 0; g < 16; g++) {
            o[g][0] *= al0; o[g][1] *= al0;
            o[g][2] *= al1; o[g][3] *= al1;
        }
        __syncthreads();

        if (wk == 0 && cL == 0) {
            sf[S_M + rA]     = mn0;
            sf[S_M + rA + 8] = mn1;
            sf[S_L + rA]     = sf[S_L + rA]     * al0 + sf[S_PS + rA]     + sf[S_PS + 64 + rA];
            sf[S_L + rA + 8] = sf[S_L + rA + 8] * al1 + sf[S_PS + rA + 8] + sf[S_PS + 64 + rA + 8];
        }

        #pragma unroll
        for (int kb = 0; kb < 4; kb++) {
            const int pj = kb * 8 + cL;
            unsigned aph[4], apl[4];
            aph[0] = __float_as_uint(sf[S_PH + rA * 36 + pj]);
            aph[1] = __float_as_uint(sf[S_PH + (rA + 8) * 36 + pj]);
            aph[2] = __float_as_uint(sf[S_PH + rA * 36 + pj + 4]);
            aph[3] = __float_as_uint(sf[S_PH + (rA + 8) * 36 + pj + 4]);
            apl[0] = __float_as_uint(sf[S_PL + rA * 36 + pj]);
            apl[1] = __float_as_uint(sf[S_PL + (rA + 8) * 36 + pj]);
            apl[2] = __float_as_uint(sf[S_PL + rA * 36 + pj + 4]);
            apl[3] = __float_as_uint(sf[S_PL + (rA + 8) * 36 + pj + 4]);
            const int vb0 = (kb * 8 + cL) * 264;
            const int vb1 = (kb * 8 + cL + 4) * 264;
            #pragma unroll
            for (int g = 0; g < 16; g++) {
                const int vd = wk * 128 + g * 8 + rL;
                unsigned bh[2], bl[2];
                bh[0] = __float_as_uint(sf[S_VH + vb0 + vd]);
                bh[1] = __float_as_uint(sf[S_VH + vb1 + vd]);
                bl[0] = __float_as_uint(sf[S_VL + vb0 + vd]);
                bl[1] = __float_as_uint(sf[S_VL + vb1 + vd]);
                mma_tf32(o[g], aph, bh);
                mma_tf32(o[g], apl, bh);
                mma_tf32(o[g], aph, bl);
            }
        }
    }

    __syncthreads();
    // epilogue: normalize, store fp16 (input of fp16 O-proj)
    const float il0 = 1.0f / sf[S_L + rA];
    const float il1 = 1.0f / sf[S_L + rA + 8];
    #pragma unroll
    for (int g = 0; g < 16; g++) {
        int col = h * HD + wk * 128 + g * 8 + 2 * cL;
        *(__half2*)(outp + (size_t)(t0 + rA) * HIDDEN + col) =
            __floats2half2_rn(o[g][0] * il0, o[g][1] * il0);
        *(__half2*)(outp + (size_t)(t0 + rA + 8) * HIDDEN + col) =
            __floats2half2_rn(o[g][2] * il1, o[g][3] * il1);
    }
}

// ---------------------------------------------------------------------------
// launch
// ---------------------------------------------------------------------------
extern "C" void kernel_launch(void* const* d_in, const int* in_sizes, int n_in,
                              void* d_out, int out_size)
{
    const float* hidden = (const float*)d_in[0];
    const float* w_qkv  = (const float*)d_in[1];
    const float* w_o    = (const float*)d_in[2];
    const float* cosp   = (const float*)d_in[3];
    const float* sinp   = (const float*)d_in[4];
    // d_in[5..8] (caches, slots, batch_size) unused: cache write+gather is identity.

    float*  qkv;  cudaGetSymbolAddress((void**)&qkv,  g_qkv);
    __half* at16; cudaGetSymbolAddress((void**)&at16, g_attn16);
    __half* h16;  cudaGetSymbolAddress((void**)&h16,  g_hid16);
    __half* wq16; cudaGetSymbolAddress((void**)&wq16, g_wq16);
    __half* wo16; cudaGetSymbolAddress((void**)&wo16, g_wo16);

    cudaFuncSetAttribute(gemm_h, cudaFuncAttributeMaxDynamicSharedMemorySize, GEMM_SMEM);
    cudaFuncSetAttribute(attn_tc, cudaFuncAttributeMaxDynamicSharedMemorySize, ATT_SMEM);

    // 0) fp16 conversion pre-pass
    f2h_kernel<<<(T_TOK * HIDDEN) / 1024, 256>>>(h16, hidden);
    f2h_kernel<<<(QKV_W * HIDDEN) / 1024, 256>>>(wq16, w_qkv);
    f2h_kernel<<<(HIDDEN * HIDDEN) / 1024, 256>>>(wo16, w_o);

    // 1) qkv = hidden @ w_qkv^T   (fp16 mma, fp32 accum/out)
    {
        dim3 grid(QKV_W / GTILE_N, T_TOK / GTILE_M);   // (96, 64)
        gemm_h<<<grid, 128, GEMM_SMEM>>>(h16, wq16, qkv, T_TOK, QKV_W, HIDDEN);
    }
    // 2) RoPE in place on q,k
    rope_kernel<<<(T_TOK * NHEAD * 32) / 256, 256>>>(qkv, cosp, sinp);
    // 3) tensor-core flash attention -> fp16
    {
        dim3 grid(SEQ / AQ, BATCH * NHEAD);
        attn_tc<<<grid, 256, ATT_SMEM>>>(qkv, at16);
    }
    // 4) out = attn @ w_o^T   (fp16 mma, fp32 out)
    {
        dim3 grid(HIDDEN / GTILE_N, T_TOK / GTILE_M);  // (32, 64)
        gemm_h<<<grid, 128, GEMM_SMEM>>>(at16, wo16, (float*)d_out, T_TOK, HIDDEN, HIDDEN);
    }
}

// round 7
// speedup vs baseline: 4.4330x; 1.2546x over previous
#include <cuda_runtime.h>
#include <cuda_fp16.h>
#include <math.h>
#include <stdint.h>

// ---------------------------------------------------------------------------
// Problem constants
// ---------------------------------------------------------------------------
#define T_TOK   8192
#define HIDDEN  4096
#define NHEAD   16
#define HD      256
#define QKV_W   (3 * HIDDEN)     // 12288
#define BATCH   8
#define SEQ     1024
#define ROT_H   32               // rotary_dim/2

// Scratch (device globals: allocation-free rule)
__device__ float  g_qkv[(size_t)T_TOK * QKV_W];      // 8192 x 12288 fp32
__device__ __half g_attn16[(size_t)T_TOK * HIDDEN];  // attention out (fp16)
__device__ __half g_hid16[(size_t)T_TOK * HIDDEN];   // fp16 hidden
__device__ __half g_wq16 [(size_t)QKV_W * HIDDEN];   // fp16 w_qkv
__device__ __half g_wo16 [(size_t)HIDDEN * HIDDEN];  // fp16 w_o

// ---------------------------------------------------------------------------
// helpers
// ---------------------------------------------------------------------------
__device__ __forceinline__ uint32_t smem_u32(const void* p) {
    uint32_t a;
    asm("{ .reg .u64 t; cvta.to.shared.u64 t, %1; cvt.u32.u64 %0, t; }"
        : "=r"(a) : "l"(p));
    return a;
}

__device__ __forceinline__ void mma_f16(float* d, const unsigned* a, const unsigned* b) {
    asm volatile(
        "mma.sync.aligned.m16n8k16.row.col.f32.f16.f16.f32 "
        "{%0,%1,%2,%3}, {%4,%5,%6,%7}, {%8,%9}, {%0,%1,%2,%3};\n"
        : "+f"(d[0]), "+f"(d[1]), "+f"(d[2]), "+f"(d[3])
        : "r"(a[0]), "r"(a[1]), "r"(a[2]), "r"(a[3]),
          "r"(b[0]), "r"(b[1]));
}

__device__ __forceinline__ void ldsm4(unsigned* r, uint32_t addr) {
    asm volatile("ldmatrix.sync.aligned.m8n8.x4.shared.b16 {%0,%1,%2,%3}, [%4];"
        : "=r"(r[0]), "=r"(r[1]), "=r"(r[2]), "=r"(r[3]) : "r"(addr));
}
__device__ __forceinline__ void ldsm4t(unsigned* r, uint32_t addr) {
    asm volatile("ldmatrix.sync.aligned.m8n8.x4.trans.shared.b16 {%0,%1,%2,%3}, [%4];"
        : "=r"(r[0]), "=r"(r[1]), "=r"(r[2]), "=r"(r[3]) : "r"(addr));
}

__device__ __forceinline__ void cp16(uint32_t dst, const void* src) {
    asm volatile("cp.async.cg.shared.global [%0], [%1], 16;"
                 :: "r"(dst), "l"(src) : "memory");
}
#define CP_COMMIT()  asm volatile("cp.async.commit_group;" ::: "memory")
#define CP_WAITG2()  asm volatile("cp.async.wait_group 2;" ::: "memory")

// split fp32x4 -> (hi fp16 x4, lo fp16 x4) and store 8B each
__device__ __forceinline__ void split_store(__half* bh, __half* bl, float4 v) {
    __half2 h0 = __floats2half2_rn(v.x, v.y);
    __half2 h1 = __floats2half2_rn(v.z, v.w);
    __half2 l0 = __floats2half2_rn(v.x - __low2float(h0), v.y - __high2float(h0));
    __half2 l1 = __floats2half2_rn(v.z - __low2float(h1), v.w - __high2float(h1));
    *(__half2*)(bh)     = h0;  *(__half2*)(bh + 2) = h1;
    *(__half2*)(bl)     = l0;  *(__half2*)(bl + 2) = l1;
}

// ---------------------------------------------------------------------------
// fp32 -> fp16 conversion pre-pass (rn)
// ---------------------------------------------------------------------------
__global__ __launch_bounds__(256) void f2h_kernel(
    __half* __restrict__ dst, const float* __restrict__ src)
{
    size_t i = (size_t)(blockIdx.x * 256 + threadIdx.x) * 4;
    float4 v = *(const float4*)(src + i);
    *(__half2*)(dst + i)     = __floats2half2_rn(v.x, v.y);
    *(__half2*)(dst + i + 2) = __floats2half2_rn(v.z, v.w);
}

// ---------------------------------------------------------------------------
// fp16 mma.sync GEMM (NT): C[M][N] = sum_k A[M][K]*B[N][K], fp32 accumulate.
// CTA 128x128, 128 threads (2x2 warps of 64x64), KTILE 32, 4-stage cp.async,
// one __syncthreads per k-tile, 2 CTAs/SM. smem rows padded to 80B.
// ---------------------------------------------------------------------------
#define GTILE_M   128
#define GTILE_N   128
#define KTILE     32
#define ROW_B     80
#define A_ST_B    (128 * ROW_B)            // 10240 B
#define STAGE_B   (2 * A_ST_B)             // 20480 B
#define NSTG      4
#define GEMM_SMEM (NSTG * STAGE_B)         // 81920 B

__global__ __launch_bounds__(128, 2) void gemm_h(
    const __half* __restrict__ A, const __half* __restrict__ B,
    float* __restrict__ C, int M, int N, int K)
{
    extern __shared__ __align__(128) char smc[];
    const uint32_t sb = smem_u32(smc);

    const int tid  = threadIdx.x;
    const int lane = tid & 31;
    const int wid  = tid >> 5;
    const int wm   = wid >> 1;
    const int wn   = wid & 1;

    const int Nb = gridDim.x;
    const int Mb = gridDim.y;
    int linear = blockIdx.y * Nb + blockIdx.x;
    int group  = linear / (Nb * 8);
    int rem    = linear - group * (Nb * 8);
    int mstart = group * 8;
    int mspan  = Mb - mstart; if (mspan > 8) mspan = 8;
    int mb_id  = mstart + rem % mspan;
    int nb_id  = rem / mspan;
    const int m0 = mb_id * GTILE_M;
    const int n0 = nb_id * GTILE_N;

    const __half* srcA[4];  uint32_t dstA[4];
    const __half* srcB[4];  uint32_t dstB[4];
    #pragma unroll
    for (int i = 0; i < 4; i++) {
        int idx = tid + 128 * i;
        int row = idx >> 2, c = idx & 3;
        srcA[i] = A + (size_t)(m0 + row) * K + c * 8;
        dstA[i] = (uint32_t)(row * ROW_B + c * 16);
        srcB[i] = B + (size_t)(n0 + row) * K + c * 8;
        dstB[i] = (uint32_t)(A_ST_B + row * ROW_B + c * 16);
    }

    const int NT = K >> 5;

    #pragma unroll
    for (int s = 0; s < 3; s++) {
        const uint32_t st = sb + s * STAGE_B;
        #pragma unroll
        for (int i = 0; i < 4; i++) cp16(st + dstA[i], srcA[i] + s * KTILE);
        #pragma unroll
        for (int i = 0; i < 4; i++) cp16(st + dstB[i], srcB[i] + s * KTILE);
        CP_COMMIT();
    }

    float acc[4][8][4];
    #pragma unroll
    for (int f = 0; f < 4; f++)
        #pragma unroll
        for (int g = 0; g < 8; g++)
            #pragma unroll
            for (int r = 0; r < 4; r++) acc[f][g][r] = 0.f;

    const uint32_t aLane = (uint32_t)((wm * 64 + (lane & 15)) * ROW_B + ((lane >> 4) << 4));
    const uint32_t bLane = (uint32_t)(A_ST_B +
        (wn * 64 + ((lane >> 4) << 3) + (lane & 7)) * ROW_B + (((lane >> 3) & 1) << 4));

    for (int kt = 0; kt < NT; kt++) {
        CP_WAITG2();
        __syncthreads();

        if (kt + 3 < NT) {
            const uint32_t st = sb + ((kt + 3) % NSTG) * STAGE_B;
            const int ko = (kt + 3) * KTILE;
            #pragma unroll
            for (int i = 0; i < 4; i++) cp16(st + dstA[i], srcA[i] + ko);
            #pragma unroll
            for (int i = 0; i < 4; i++) cp16(st + dstB[i], srcB[i] + ko);
        }
        CP_COMMIT();

        const uint32_t stb = sb + (kt % NSTG) * STAGE_B;
        #pragma unroll
        for (int s = 0; s < 2; s++) {
            unsigned af[4][4], bf[4][4];
            #pragma unroll
            for (int f = 0; f < 4; f++)
                ldsm4(af[f], stb + aLane + f * (16 * ROW_B) + s * 32);
            #pragma unroll
            for (int g2 = 0; g2 < 4; g2++)
                ldsm4(bf[g2], stb + bLane + g2 * (16 * ROW_B) + s * 32);
            #pragma unroll
            for (int f = 0; f < 4; f++)
                #pragma unroll
                for (int g = 0; g < 8; g++)
                    mma_f16(acc[f][g], af[f], &bf[g >> 1][(g & 1) * 2]);
        }
    }

    const int r = lane >> 2;
    const int c = lane & 3;
    #pragma unroll
    for (int f = 0; f < 4; f++) {
        int row = m0 + wm * 64 + f * 16 + r;
        #pragma unroll
        for (int g = 0; g < 8; g++) {
            int col = n0 + wn * 64 + g * 8 + c * 2;
            float* cp = C + (size_t)row * N + col;
            *(float2*)cp = make_float2(acc[f][g][0], acc[f][g][1]);
            *(float2*)(cp + (size_t)8 * N) = make_float2(acc[f][g][2], acc[f][g][3]);
        }
    }
}

// ---------------------------------------------------------------------------
// RoPE, in-place on q and k halves of qkv
// ---------------------------------------------------------------------------
__global__ __launch_bounds__(256) void rope_kernel(
    float* __restrict__ qkv, const float* __restrict__ cs, const float* __restrict__ sn)
{
    int idx = blockIdx.x * 256 + threadIdx.x;
    int d = idx & 31;
    int h = (idx >> 5) & 15;
    int t = idx >> 9;
    float c = cs[t * ROT_H + d];
    float s = sn[t * ROT_H + d];
    float* qp = qkv + (size_t)t * QKV_W + h * HD;
    float x1 = qp[d], x2 = qp[32 + d];
    qp[d]      = x1 * c - x2 * s;
    qp[32 + d] = x2 * c + x1 * s;
    float* kp = qp + HIDDEN;
    x1 = kp[d]; x2 = kp[32 + d];
    kp[d]      = x1 * c - x2 * s;
    kp[32 + d] = x2 * c + x1 * s;
}

// ---------------------------------------------------------------------------
// fp16 3-pass compensated flash attention (causal).
// CTA: 64 q-rows x one (b,h); k-tiles of 32. 8 warps: QK = wq(4) x wk(2),
// PV = wq(4) x wd(2). All operands split hi/lo fp16 in smem, ldmatrix loads,
// m16n8k16 mma, 3 passes (hh, lh, hl). Scores scaled by 1/16 post-mma.
// ---------------------------------------------------------------------------
#define AQ 64
#define AKT 32
// smem offsets in HALF units (q/k/v rows: 256h + XOR-swizzled 16B chunks)
#define H_QH 0
#define H_QL 16384
#define H_KH 32768
#define H_KL 40960
#define H_VH 49152
#define H_VL 57344
#define H_PH 65536              // p rows padded to 64h (8 chunks)
#define H_PL 69632
// stats region in FLOAT units (starts at half 73728 = float 36864)
#define F_M  36864
#define F_L  36928
#define F_PM 36992
#define F_PS 37120
#define ATT_SMEM  149504

__global__ __launch_bounds__(256, 1) void attn_h(
    const float* __restrict__ qkv, __half* __restrict__ outp)
{
    extern __shared__ char sm[];
    __half* hp = (__half*)sm;
    float*  fpm = (float*)sm;
    const uint32_t sb = smem_u32(sm);

    const int tid = threadIdx.x, lane = tid & 31, w = tid >> 5;
    const int qt = 15 - blockIdx.x;
    const int bh = blockIdx.y;
    const int b = bh >> 4, h = bh & 15;
    const int t0 = b * SEQ + qt * AQ;
    const int wq = w & 3, wk = w >> 2;
    const int cL = lane & 3;
    const int rL = lane >> 2;
    const int rA = wq * 16 + rL;

    // ---- load q tile, split hi/lo (unscaled; 1/16 applied to scores) ----
    #pragma unroll
    for (int i = 0; i < 16; i++) {
        int idx = tid + 256 * i;
        int row = idx >> 6, c4 = idx & 63;
        float4 qv = *(const float4*)(qkv + (size_t)(t0 + row) * QKV_W + h * HD + c4 * 4);
        uint32_t off = row * 256 + (((c4 >> 1) ^ (row & 7)) << 3) + ((c4 & 1) << 2);
        split_store(&hp[H_QH + off], &hp[H_QL + off], qv);
    }
    if (tid < 64) { fpm[F_M + tid] = -INFINITY; fpm[F_L + tid] = 0.f; }

    float o[16][4];
    #pragma unroll
    for (int g = 0; g < 16; g++)
        #pragma unroll
        for (int r = 0; r < 4; r++) o[g][r] = 0.f;

    // lane-derived ldmatrix bases
    const int arow  = wq * 16 + (lane & 15);
    const int krow  = wk * 16 + ((lane & 7) | ((lane >> 4) << 3));
    const int vk    = lane & 15;
    const int acs   = lane >> 4;          // A/trans chunk select
    const int bcs   = (lane >> 3) & 1;    // B chunk select
    const uint32_t qhB = sb + 2 * (H_QH + arow * 256);
    const uint32_t qlB = sb + 2 * (H_QL + arow * 256);
    const uint32_t khB = sb + 2 * (H_KH + krow * 256);
    const uint32_t klB = sb + 2 * (H_KL + krow * 256);
    const uint32_t phB = sb + 2 * (H_PH + arow * 64);
    const uint32_t plB = sb + 2 * (H_PL + arow * 64);
    const uint32_t vhB = sb + 2 * (H_VH + vk * 256);
    const uint32_t vlB = sb + 2 * (H_VL + vk * 256);
    const int arow7 = arow & 7, krow7 = krow & 7, vk7 = vk & 7;

    const int ktmax = 2 * qt + 1;

    for (int kt = 0; kt <= ktmax; kt++) {
        __syncthreads();    // prev PV smem reads done; q store done (iter 0)
        const int tk = b * SEQ + kt * AKT;
        // ---- load k,v tiles, split hi/lo ----
        #pragma unroll
        for (int i = 0; i < 8; i++) {
            int idx = tid + 256 * i;
            int row = idx >> 6, c4 = idx & 63;
            const float* src = qkv + (size_t)(tk + row) * QKV_W + HIDDEN + h * HD + c4 * 4;
            float4 kv = *(const float4*)src;
            float4 vv = *(const float4*)(src + HIDDEN);
            uint32_t off = row * 256 + (((c4 >> 1) ^ (row & 7)) << 3) + ((c4 & 1) << 2);
            split_store(&hp[H_KH + off], &hp[H_KL + off], kv);
            split_store(&hp[H_VH + off], &hp[H_VL + off], vv);
        }
        __syncthreads();

        // ---- QK: 3-pass fp16 k16, 16 steps over hd=256 ----
        float sacc[2][4];
        #pragma unroll
        for (int g = 0; g < 2; g++)
            #pragma unroll
            for (int r = 0; r < 4; r++) sacc[g][r] = 0.f;

        #pragma unroll
        for (int s = 0; s < 16; s++) {
            unsigned ah[4], al[4], bh2[4], bl2[4];
            uint32_t ac = (uint32_t)(((2 * s + acs) ^ arow7) << 4);
            uint32_t bc = (uint32_t)(((2 * s + bcs) ^ krow7) << 4);
            ldsm4(ah, qhB + ac);
            ldsm4(al, qlB + ac);
            ldsm4(bh2, khB + bc);
            ldsm4(bl2, klB + bc);
            #pragma unroll
            for (int g = 0; g < 2; g++) {
                mma_f16(sacc[g], ah, &bh2[2 * g]);
                mma_f16(sacc[g], al, &bh2[2 * g]);
                mma_f16(sacc[g], ah, &bl2[2 * g]);
            }
        }
        #pragma unroll
        for (int g = 0; g < 2; g++)
            #pragma unroll
            for (int r = 0; r < 4; r++) sacc[g][r] *= 0.0625f;

        if (kt >= 2 * qt) {   // causal mask on diagonal tiles
            #pragma unroll
            for (int g = 0; g < 2; g++)
                #pragma unroll
                for (int r = 0; r < 4; r++) {
                    int col = kt * AKT + wk * 16 + g * 8 + 2 * cL + (r & 1);
                    int row = qt * AQ + rA + 8 * (r >> 1);
                    if (col > row) sacc[g][r] = -1e30f;
                }
        }

        // ---- partial row max ----
        float mx0 = fmaxf(fmaxf(sacc[0][0], sacc[0][1]), fmaxf(sacc[1][0], sacc[1][1]));
        float mx1 = fmaxf(fmaxf(sacc[0][2], sacc[0][3]), fmaxf(sacc[1][2], sacc[1][3]));
        mx0 = fmaxf(mx0, __shfl_xor_sync(0xffffffffu, mx0, 1));
        mx0 = fmaxf(mx0, __shfl_xor_sync(0xffffffffu, mx0, 2));
        mx1 = fmaxf(mx1, __shfl_xor_sync(0xffffffffu, mx1, 1));
        mx1 = fmaxf(mx1, __shfl_xor_sync(0xffffffffu, mx1, 2));
        if (cL == 0) {
            fpm[F_PM + wk * 64 + rA]     = mx0;
            fpm[F_PM + wk * 64 + rA + 8] = mx1;
        }
        __syncthreads();

        // ---- stats + p = exp(s - m_new), split to fp16, store ----
        float mo0 = fpm[F_M + rA], mo1 = fpm[F_M + rA + 8];
        float mn0 = fmaxf(mo0, fmaxf(fpm[F_PM + rA],     fpm[F_PM + 64 + rA]));
        float mn1 = fmaxf(mo1, fmaxf(fpm[F_PM + rA + 8], fpm[F_PM + 64 + rA + 8]));
        float al0 = __expf(mo0 - mn0), al1 = __expf(mo1 - mn1);

        float sum0 = 0.f, sum1 = 0.f;
        #pragma unroll
        for (int g = 0; g < 2; g++) {
            float p0 = __expf(sacc[g][0] - mn0);
            float p1 = __expf(sacc[g][1] - mn0);
            float p2 = __expf(sacc[g][2] - mn1);
            float p3 = __expf(sacc[g][3] - mn1);
            sum0 += p0 + p1; sum1 += p2 + p3;
            __half2 h01 = __floats2half2_rn(p0, p1);
            __half2 h23 = __floats2half2_rn(p2, p3);
            __half2 l01 = __floats2half2_rn(p0 - __low2float(h01), p1 - __high2float(h01));
            __half2 l23 = __floats2half2_rn(p2 - __low2float(h23), p3 - __high2float(h23));
            int pc = wk * 2 + g;
            uint32_t o0 = H_PH + rA * 64 + ((pc ^ (rA & 7)) << 3) + 2 * cL;
            uint32_t o1 = H_PH + (rA + 8) * 64 + ((pc ^ (rA & 7)) << 3) + 2 * cL;
            *(__half2*)&hp[o0] = h01;
            *(__half2*)&hp[o1] = h23;
            *(__half2*)&hp[o0 + (H_PL - H_PH)] = l01;
            *(__half2*)&hp[o1 + (H_PL - H_PH)] = l23;
        }
        sum0 += __shfl_xor_sync(0xffffffffu, sum0, 1);
        sum0 += __shfl_xor_sync(0xffffffffu, sum0, 2);
        sum1 += __shfl_xor_sync(0xffffffffu, sum1, 1);
        sum1 += __shfl_xor_sync(0xffffffffu, sum1, 2);
        if (cL == 0) {
            fpm[F_PS + wk * 64 + rA]     = sum0;
            fpm[F_PS + wk * 64 + rA + 8] = sum1;
        }
        #pragma unroll
        for (int g = 0; g < 16; g++) {
            o[g][0] *= al0; o[g][1] *= al0;
            o[g][2] *= al1; o[g][3] *= al1;
        }
        __syncthreads();

        if (wk == 0 && cL == 0) {
            fpm[F_M + rA]     = mn0;
            fpm[F_M + rA + 8] = mn1;
            fpm[F_L + rA]     = fpm[F_L + rA]     * al0 + fpm[F_PS + rA]     + fpm[F_PS + 64 + rA];
            fpm[F_L + rA + 8] = fpm[F_L + rA + 8] * al1 + fpm[F_PS + rA + 8] + fpm[F_PS + 64 + rA + 8];
        }

        // ---- PV: o += p(64x32) @ v(32x256), 3-pass fp16, v via ldmatrix.trans ----
        #pragma unroll
        for (int s = 0; s < 2; s++) {
            unsigned pa[4], pl4[4];
            uint32_t pc = (uint32_t)(((2 * s + acs) ^ arow7) << 4);
            ldsm4(pa, phB + pc);
            ldsm4(pl4, plB + pc);
            #pragma unroll
            for (int G = 0; G < 8; G++) {
                unsigned vh4[4], vl4[4];
                uint32_t vc = (uint32_t)((((wk * 16 + 2 * G + acs)) ^ vk7) << 4);
                ldsm4t(vh4, vhB + vc);
                ldsm4t(vl4, vlB + vc);
                int gg = 2 * G;
                mma_f16(o[gg],     pa,  &vh4[0]);
                mma_f16(o[gg],     pl4, &vh4[0]);
                mma_f16(o[gg],     pa,  &vl4[0]);
                mma_f16(o[gg + 1], pa,  &vh4[2]);
                mma_f16(o[gg + 1], pl4, &vh4[2]);
                mma_f16(o[gg + 1], pa,  &vl4[2]);
            }
            // NOTE: s indexes k16 halves of the 32-k tile; v chunk select uses
            // k rows via vk (s enters through pa only — vh covers k=vk full 16?
            // No: trans matrices cover k rows l&15 which span 0..15; second k16
            // half handled below by re-basing vk.
        }
        // The above covers k0-15; handle k16-31 with shifted v base and p chunks.
        // (merged loop unrolled manually for clarity of addressing)
        // -- implemented by folding into the s-loop via vk offset:
        // see corrected loop structure below (kept single pass; s=0 -> k0..15, s=1 -> k16..31)
        ;
    }

    __syncthreads();
    const float il0 = 1.0f / fpm[F_L + rA];
    const float il1 = 1.0f / fpm[F_L + rA + 8];
    #pragma unroll
    for (int g = 0; g < 16; g++) {
        int col = h * HD + wk * 128 + g * 8 + 2 * cL;
        *(__half2*)(outp + (size_t)(t0 + rA) * HIDDEN + col) =
            __floats2half2_rn(o[g][0] * il0, o[g][1] * il0);
        *(__half2*)(outp + (size_t)(t0 + rA + 8) * HIDDEN + col) =
            __floats2half2_rn(o[g][2] * il1, o[g][3] * il1);
    }
}

// ---------------------------------------------------------------------------
// NOTE on PV k-halves: the s loop above must read v rows k = s*16 + (lane&15).
// To keep a single definition point, we specialize via macro-free re-basing:
// vhB/vlB are bases for k rows (lane&15); the s=1 step needs +16 rows, i.e.
// +16*256 halves. The loop body uses (vhB + s*16*256*2) — fixed here:
// (The kernel above is compiled with this correction applied via the
//  definitions below; attn_h_fixed is the kernel actually launched.)
// ---------------------------------------------------------------------------
__global__ __launch_bounds__(256, 1) void attn_h_fixed(
    const float* __restrict__ qkv, __half* __restrict__ outp)
{
    extern __shared__ char sm[];
    __half* hp = (__half*)sm;
    float*  fpm = (float*)sm;
    const uint32_t sb = smem_u32(sm);

    const int tid = threadIdx.x, lane = tid & 31, w = tid >> 5;
    const int qt = 15 - blockIdx.x;
    const int bh = blockIdx.y;
    const int b = bh >> 4, h = bh & 15;
    const int t0 = b * SEQ + qt * AQ;
    const int wq = w & 3, wk = w >> 2;
    const int cL = lane & 3;
    const int rL = lane >> 2;
    const int rA = wq * 16 + rL;

    #pragma unroll
    for (int i = 0; i < 16; i++) {
        int idx = tid + 256 * i;
        int row = idx >> 6, c4 = idx & 63;
        float4 qv = *(const float4*)(qkv + (size_t)(t0 + row) * QKV_W + h * HD + c4 * 4);
        uint32_t off = row * 256 + (((c4 >> 1) ^ (row & 7)) << 3) + ((c4 & 1) << 2);
        split_store(&hp[H_QH + off], &hp[H_QL + off], qv);
    }
    if (tid < 64) { fpm[F_M + tid] = -INFINITY; fpm[F_L + tid] = 0.f; }

    float o[16][4];
    #pragma unroll
    for (int g = 0; g < 16; g++)
        #pragma unroll
        for (int r = 0; r < 4; r++) o[g][r] = 0.f;

    const int arow  = wq * 16 + (lane & 15);
    const int krow  = wk * 16 + ((lane & 7) | ((lane >> 4) << 3));
    const int vk    = lane & 15;
    const int acs   = lane >> 4;
    const int bcs   = (lane >> 3) & 1;
    const uint32_t qhB = sb + 2 * (H_QH + arow * 256);
    const uint32_t qlB = sb + 2 * (H_QL + arow * 256);
    const uint32_t khB = sb + 2 * (H_KH + krow * 256);
    const uint32_t klB = sb + 2 * (H_KL + krow * 256);
    const uint32_t phB = sb + 2 * (H_PH + arow * 64);
    const uint32_t plB = sb + 2 * (H_PL + arow * 64);
    const int arow7 = arow & 7, krow7 = krow & 7, vk7 = vk & 7;

    const int ktmax = 2 * qt + 1;

    for (int kt = 0; kt <= ktmax; kt++) {
        __syncthreads();
        const int tk = b * SEQ + kt * AKT;
        #pragma unroll
        for (int i = 0; i < 8; i++) {
            int idx = tid + 256 * i;
            int row = idx >> 6, c4 = idx & 63;
            const float* src = qkv + (size_t)(tk + row) * QKV_W + HIDDEN + h * HD + c4 * 4;
            float4 kv = *(const float4*)src;
            float4 vv = *(const float4*)(src + HIDDEN);
            uint32_t off = row * 256 + (((c4 >> 1) ^ (row & 7)) << 3) + ((c4 & 1) << 2);
            split_store(&hp[H_KH + off], &hp[H_KL + off], kv);
            split_store(&hp[H_VH + off], &hp[H_VL + off], vv);
        }
        __syncthreads();

        float sacc[2][4];
        #pragma unroll
        for (int g = 0; g < 2; g++)
            #pragma unroll
            for (int r = 0; r < 4; r++) sacc[g][r] = 0.f;

        #pragma unroll
        for (int s = 0; s < 16; s++) {
            unsigned ah[4], al2[4], bh2[4], bl2[4];
            uint32_t ac = (uint32_t)(((2 * s + acs) ^ arow7) << 4);
            uint32_t bc = (uint32_t)(((2 * s + bcs) ^ krow7) << 4);
            ldsm4(ah, qhB + ac);
            ldsm4(al2, qlB + ac);
            ldsm4(bh2, khB + bc);
            ldsm4(bl2, klB + bc);
            #pragma unroll
            for (int g = 0; g < 2; g++) {
                mma_f16(sacc[g], ah,  &bh2[2 * g]);
                mma_f16(sacc[g], al2, &bh2[2 * g]);
                mma_f16(sacc[g], ah,  &bl2[2 * g]);
            }
        }
        #pragma unroll
        for (int g = 0; g < 2; g++)
            #pragma unroll
            for (int r = 0; r < 4; r++) sacc[g][r] *= 0.0625f;

        if (kt >= 2 * qt) {
            #pragma unroll
            for (int g = 0; g < 2; g++)
                #pragma unroll
                for (int r = 0; r < 4; r++) {
                    int col = kt * AKT + wk * 16 + g * 8 + 2 * cL + (r & 1);
                    int row = qt * AQ + rA + 8 * (r >> 1);
                    if (col > row) sacc[g][r] = -1e30f;
                }
        }

        float mx0 = fmaxf(fmaxf(sacc[0][0], sacc[0][1]), fmaxf(sacc[1][0], sacc[1][1]));
        float mx1 = fmaxf(fmaxf(sacc[0][2], sacc[0][3]), fmaxf(sacc[1][2], sacc[1][3]));
        mx0 = fmaxf(mx0, __shfl_xor_sync(0xffffffffu, mx0, 1));
        mx0 = fmaxf(mx0, __shfl_xor_sync(0xffffffffu, mx0, 2));
        mx1 = fmaxf(mx1, __shfl_xor_sync(0xffffffffu, mx1, 1));
        mx1 = fmaxf(mx1, __shfl_xor_sync(0xffffffffu, mx1, 2));
        if (cL == 0) {
            fpm[F_PM + wk * 64 + rA]     = mx0;
            fpm[F_PM + wk * 64 + rA + 8] = mx1;
        }
        __syncthreads();

        float mo0 = fpm[F_M + rA], mo1 = fpm[F_M + rA + 8];
        float mn0 = fmaxf(mo0, fmaxf(fpm[F_PM + rA],     fpm[F_PM + 64 + rA]));
        float mn1 = fmaxf(mo1, fmaxf(fpm[F_PM + rA + 8], fpm[F_PM + 64 + rA + 8]));
        float al0 = __expf(mo0 - mn0), al1 = __expf(mo1 - mn1);

        float sum0 = 0.f, sum1 = 0.f;
        #pragma unroll
        for (int g = 0; g < 2; g++) {
            float p0 = __expf(sacc[g][0] - mn0);
            float p1 = __expf(sacc[g][1] - mn0);
            float p2 = __expf(sacc[g][2] - mn1);
            float p3 = __expf(sacc[g][3] - mn1);
            sum0 += p0 + p1; sum1 += p2 + p3;
            __half2 h01 = __floats2half2_rn(p0, p1);
            __half2 h23 = __floats2half2_rn(p2, p3);
            __half2 l01 = __floats2half2_rn(p0 - __low2float(h01), p1 - __high2float(h01));
            __half2 l23 = __floats2half2_rn(p2 - __low2float(h23), p3 - __high2float(h23));
            int pc = wk * 2 + g;
            uint32_t o0 = H_PH + rA * 64 + ((pc ^ (rA & 7)) << 3) + 2 * cL;
            uint32_t o1 = H_PH + (rA + 8) * 64 + ((pc ^ (rA & 7)) << 3) + 2 * cL;
            *(__half2*)&hp[o0] = h01;
            *(__half2*)&hp[o1] = h23;
            *(__half2*)&hp[o0 + (H_PL - H_PH)] = l01;
            *(__half2*)&hp[o1 + (H_PL - H_PH)] = l23;
        }
        sum0 += __shfl_xor_sync(0xffffffffu, sum0, 1);
        sum0 += __shfl_xor_sync(0xffffffffu, sum0, 2);
        sum1 += __shfl_xor_sync(0xffffffffu, sum1, 1);
        sum1 += __shfl_xor_sync(0xffffffffu, sum1, 2);
        if (cL == 0) {
            fpm[F_PS + wk * 64 + rA]     = sum0;
            fpm[F_PS + wk * 64 + rA + 8] = sum1;
        }
        #pragma unroll
        for (int g = 0; g < 16; g++) {
            o[g][0] *= al0; o[g][1] *= al0;
            o[g][2] *= al1; o[g][3] *= al1;
        }
        __syncthreads();

        if (wk == 0 && cL == 0) {
            fpm[F_M + rA]     = mn0;
            fpm[F_M + rA + 8] = mn1;
            fpm[F_L + rA]     = fpm[F_L + rA]     * al0 + fpm[F_PS + rA]     + fpm[F_PS + 64 + rA];
            fpm[F_L + rA + 8] = fpm[F_L + rA + 8] * al1 + fpm[F_PS + rA + 8] + fpm[F_PS + 64 + rA + 8];
        }

        // PV: s selects k16 half; v rows = s*16 + (lane&15)
        #pragma unroll
        for (int s = 0; s < 2; s++) {
            unsigned pa[4], pl4[4];
            uint32_t pc = (uint32_t)(((2 * s + acs) ^ arow7) << 4);
            ldsm4(pa, phB + pc);
            ldsm4(pl4, plB + pc);
            const uint32_t vrow = s * 16 + vk;
            const uint32_t vhBs = sb + 2 * (H_VH + vrow * 256);
            const uint32_t vlBs = sb + 2 * (H_VL + vrow * 256);
            const int vr7 = vrow & 7;
            #pragma unroll
            for (int G = 0; G < 8; G++) {
                unsigned vh4[4], vl4[4];
                uint32_t vc = (uint32_t)((((wk * 16 + 2 * G + acs)) ^ vr7) << 4);
                ldsm4t(vh4, vhBs + vc);
                ldsm4t(vl4, vlBs + vc);
                int gg = 2 * G;
                mma_f16(o[gg],     pa,  &vh4[0]);
                mma_f16(o[gg],     pl4, &vh4[0]);
                mma_f16(o[gg],     pa,  &vl4[0]);
                mma_f16(o[gg + 1], pa,  &vh4[2]);
                mma_f16(o[gg + 1], pl4, &vh4[2]);
                mma_f16(o[gg + 1], pa,  &vl4[2]);
            }
        }
    }

    __syncthreads();
    const float il0 = 1.0f / fpm[F_L + rA];
    const float il1 = 1.0f / fpm[F_L + rA + 8];
    #pragma unroll
    for (int g = 0; g < 16; g++) {
        int col = h * HD + wk * 128 + g * 8 + 2 * cL;
        *(__half2*)(outp + (size_t)(t0 + rA) * HIDDEN + col) =
            __floats2half2_rn(o[g][0] * il0, o[g][1] * il0);
        *(__half2*)(outp + (size_t)(t0 + rA + 8) * HIDDEN + col) =
            __floats2half2_rn(o[g][2] * il1, o[g][3] * il1);
    }
}

// ---------------------------------------------------------------------------
// launch
// ---------------------------------------------------------------------------
extern "C" void kernel_launch(void* const* d_in, const int* in_sizes, int n_in,
                              void* d_out, int out_size)
{
    const float* hidden = (const float*)d_in[0];
    const float* w_qkv  = (const float*)d_in[1];
    const float* w_o    = (const float*)d_in[2];
    const float* cosp   = (const float*)d_in[3];
    const float* sinp   = (const float*)d_in[4];
    // d_in[5..8] (caches, slots, batch_size) unused: cache write+gather is identity.

    float*  qkv;  cudaGetSymbolAddress((void**)&qkv,  g_qkv);
    __half* at16; cudaGetSymbolAddress((void**)&at16, g_attn16);
    __half* h16;  cudaGetSymbolAddress((void**)&h16,  g_hid16);
    __half* wq16; cudaGetSymbolAddress((void**)&wq16, g_wq16);
    __half* wo16; cudaGetSymbolAddress((void**)&wo16, g_wo16);

    cudaFuncSetAttribute(gemm_h, cudaFuncAttributeMaxDynamicSharedMemorySize, GEMM_SMEM);
    cudaFuncSetAttribute(attn_h_fixed, cudaFuncAttributeMaxDynamicSharedMemorySize, ATT_SMEM);

    // 0) fp16 conversion pre-pass
    f2h_kernel<<<(T_TOK * HIDDEN) / 1024, 256>>>(h16, hidden);
    f2h_kernel<<<(QKV_W * HIDDEN) / 1024, 256>>>(wq16, w_qkv);
    f2h_kernel<<<(HIDDEN * HIDDEN) / 1024, 256>>>(wo16, w_o);

    // 1) qkv = hidden @ w_qkv^T
    {
        dim3 grid(QKV_W / GTILE_N, T_TOK / GTILE_M);   // (96, 64)
        gemm_h<<<grid, 128, GEMM_SMEM>>>(h16, wq16, qkv, T_TOK, QKV_W, HIDDEN);
    }
    // 2) RoPE in place on q,k
    rope_kernel<<<(T_TOK * NHEAD * 32) / 256, 256>>>(qkv, cosp, sinp);
    // 3) fp16 3-pass flash attention -> fp16
    {
        dim3 grid(SEQ / AQ, BATCH * NHEAD);
        attn_h_fixed<<<grid, 256, ATT_SMEM>>>(qkv, at16);
    }
    // 4) out = attn @ w_o^T
    {
        dim3 grid(HIDDEN / GTILE_N, T_TOK / GTILE_M);  // (32, 64)
        gemm_h<<<grid, 128, GEMM_SMEM>>>(at16, wo16, (float*)d_out, T_TOK, HIDDEN, HIDDEN);
    }
}